// round 13
// baseline (speedup 1.0000x reference)
#include <cuda_runtime.h>
#include <cuda_bf16.h>
#include <math.h>
#include <stdint.h>

#define BB   32
#define LL   1024
#define VV   64
#define PHn  64
#define PFn  32
#define DD   128
#define KK   1024
#define NVQ  (BB*VV*PFn)
#define NROW (BB*VV*DD)

__device__ float g_mean[BB*VV];
__device__ float g_std[BB*VV];
__device__ float g_xt[(size_t)BB*VV*LL];          // x transposed [b][v][l]
__device__ float g_z2[NVQ];                       // exact fp32 |z|^2 per row
__device__ float g_c2[KK];
__device__ __nv_bfloat16 g_Zpb[(size_t)NVQ*DD];   // bf16 z_p [n][d]
__device__ __nv_bfloat16 g_Cb[(size_t)KK*DD];     // bf16 centroids [k][d]
__device__ __nv_bfloat16 g_W1b[64*256];
__device__ __nv_bfloat16 g_W2b[256*512];
__device__ __nv_bfloat16 g_W3b[512*32];
__device__ __nv_bfloat16 g_Fwb[128*128];          // bf16 fuse_w [k][n]

extern __shared__ char dynsm[];

// ===== helpers =====
__device__ __forceinline__ uint32_t smem_u32(const void* p) {
    uint32_t a;
    asm("{ .reg .u64 t; cvta.to.shared.u64 t, %1; cvt.u32.u64 %0, t; }" : "=r"(a) : "l"(p));
    return a;
}
__device__ __forceinline__ void ldsm4(uint32_t* r, uint32_t a) {
    asm volatile("ldmatrix.sync.aligned.m8n8.x4.shared.b16 {%0,%1,%2,%3}, [%4];"
        : "=r"(r[0]), "=r"(r[1]), "=r"(r[2]), "=r"(r[3]) : "r"(a));
}
__device__ __forceinline__ void ldsm4t(uint32_t* r, uint32_t a) {
    asm volatile("ldmatrix.sync.aligned.m8n8.x4.trans.shared.b16 {%0,%1,%2,%3}, [%4];"
        : "=r"(r[0]), "=r"(r[1]), "=r"(r[2]), "=r"(r[3]) : "r"(a));
}
__device__ __forceinline__ void mma_bf16(float* c, const uint32_t* a, uint32_t b0, uint32_t b1) {
    asm volatile("mma.sync.aligned.m16n8k16.row.col.f32.bf16.bf16.f32 "
        "{%0,%1,%2,%3}, {%4,%5,%6,%7}, {%8,%9}, {%0,%1,%2,%3};"
        : "+f"(c[0]), "+f"(c[1]), "+f"(c[2]), "+f"(c[3])
        : "r"(a[0]), "r"(a[1]), "r"(a[2]), "r"(a[3]), "r"(b0), "r"(b1));
}
__device__ __forceinline__ uint32_t packrelu(float x, float y, float bx, float by) {
    __nv_bfloat162 h = __float22bfloat162_rn(make_float2(fmaxf(x+bx,0.f), fmaxf(y+by,0.f)));
    return *reinterpret_cast<uint32_t*>(&h);
}
__device__ __forceinline__ void top5_ins(float* tv, int* ti, float d, int k) {
    if (d < tv[4]) {
        tv[4] = d; ti[4] = k;
        #pragma unroll
        for (int s = 4; s > 0; s--) {
            if (tv[s] < tv[s-1]) {
                float tf = tv[s]; tv[s] = tv[s-1]; tv[s-1] = tf;
                int tk = ti[s]; ti[s] = ti[s-1]; ti[s-1] = tk;
            }
        }
    }
}
#define CP_ASYNC16(dst, src) \
    asm volatile("cp.async.cg.shared.global [%0], [%1], 16;" :: "r"(dst), "l"(src))
#define CP_COMMIT() asm volatile("cp.async.commit_group;" ::: "memory")
#define CP_WAIT1()  asm volatile("cp.async.wait_group 1;" ::: "memory")
#define CP_WAIT0()  asm volatile("cp.async.wait_group 0;" ::: "memory")

// ===== K0: transpose x -> [b][v][l] =====
__global__ void __launch_bounds__(256) k_xT(const float* __restrict__ x) {
    __shared__ float tile[64][65];
    int b = blockIdx.y, l0 = blockIdx.x*64;
    int t = threadIdx.x;
    for (int i = t; i < 4096; i += 256) {
        int li = i >> 6, v = i & 63;
        tile[li][v] = x[((size_t)b*1024 + l0 + li)*64 + v];
    }
    __syncthreads();
    for (int i = t; i < 4096; i += 256) {
        int v = i >> 6, li = i & 63;
        g_xt[((size_t)b*64 + v)*1024 + l0 + li] = tile[li][v];
    }
}

// ===== K1: prep =====
__global__ void k_prep(const float* __restrict__ cent, const float* __restrict__ w1,
                       const float* __restrict__ w2, const float* __restrict__ w3,
                       const float* __restrict__ fw) {
    int blk = blockIdx.x;
    if (blk < 704) {
        int i = blk*256 + threadIdx.x;
        if (i < 16384)        g_W1b[i] = __float2bfloat16(w1[i]);
        else if (i < 147456)  g_W2b[i - 16384] = __float2bfloat16(w2[i - 16384]);
        else if (i < 163840)  g_W3b[i - 147456] = __float2bfloat16(w3[i - 147456]);
        else if (i < 180224)  g_Fwb[i - 163840] = __float2bfloat16(fw[i - 163840]);
    } else {
        int w = threadIdx.x >> 5, l = threadIdx.x & 31;
        int k = (blk - 704) * 8 + w;
        const float* cp = cent + (size_t)k*DD;
        float s = 0.f;
        #pragma unroll
        for (int q = 0; q < 4; q++) {
            float c = cp[l + 32*q];
            s += c*c;
            g_Cb[(size_t)k*DD + l + 32*q] = __float2bfloat16(c);
        }
        #pragma unroll
        for (int o = 16; o; o >>= 1) s += __shfl_xor_sync(0xffffffffu, s, o);
        if (l == 0) g_c2[k] = s;
    }
}

// ===== K3: fused encode + 3-layer HMMA MLP =====
#define MO_A   0
#define MO_W   18432
#define MO_H1  88064
#define MO_W3  155648
#define SC_XV  155648
#define SC_WS  159744
#define SMEM_MLP 196608
#define W_SUB  34816

__device__ __forceinline__ void gemm_tile64(uint32_t Abase, int sA, int m0,
                                            uint32_t Bbase, int sB, int n0,
                                            int ksteps, int l, float acc[8][4]) {
    for (int ks = 0; ks < ksteps; ks++) {
        int kk = ks*16;
        uint32_t av[4];
        ldsm4(av, Abase + (uint32_t)(((m0 + (l&15))*sA + kk + ((l>>4)<<3))*2));
        #pragma unroll
        for (int t = 0; t < 4; t++) {
            uint32_t bvv[4];
            ldsm4t(bvv, Bbase + (uint32_t)(((kk + (l&15))*sB + n0 + t*16 + ((l>>4)<<3))*2));
            mma_bf16(acc[2*t],   av, bvv[0], bvv[1]);
            mma_bf16(acc[2*t+1], av, bvv[2], bvv[3]);
        }
    }
}

__device__ __forceinline__ void epi64(float acc[8][4], char* hdst, int sH, int m0, int n0,
                                      const float* __restrict__ bias, int boff, int l) {
    int row = l >> 2, qc = (l & 3)*2;
    #pragma unroll
    for (int t8 = 0; t8 < 8; t8++) {
        int col = n0 + t8*8 + qc;
        float b0 = __ldg(&bias[boff + col]), b1 = __ldg(&bias[boff + col + 1]);
        *(uint32_t*)(hdst + ((m0+row)*sH + col)*2)   = packrelu(acc[t8][0], acc[t8][1], b0, b1);
        *(uint32_t*)(hdst + ((m0+row+8)*sH + col)*2) = packrelu(acc[t8][2], acc[t8][3], b0, b1);
    }
}

__device__ __forceinline__ void issue_w2_sub(uint32_t base, int s, int hb, int t) {
    int nc = s >> 1, ksub = s & 1;
    const uint4* W2g = reinterpret_cast<const uint4*>(g_W2b);
    #pragma unroll
    for (int rep = 0; rep < 8; rep++) {
        int i = t + rep*256;
        int row = i >> 4, q = i & 15;
        CP_ASYNC16(base + MO_W + hb*W_SUB + row*272 + q*16,
                   (const void*)(W2g + (ksub*128 + row)*64 + nc*16 + q));
    }
    CP_COMMIT();
}

__global__ void __launch_bounds__(256, 1) k_mlp_mma(
    const float* __restrict__ ew, const float* __restrict__ eb,
    const float* __restrict__ lnw, const float* __restrict__ lnb,
    const float* __restrict__ b1g, const float* __restrict__ b2g,
    const float* __restrict__ b3g) {
    char* smem = dynsm;
    uint32_t base = smem_u32(smem);
    __shared__ float red[16], stat[2];
    int t = threadIdx.x, w = t >> 5, l = t & 31;
    int bv = blockIdx.x;

    // group 0: x tile + enc_w + W1
    {
        const uint4* Xg = reinterpret_cast<const uint4*>(g_xt + (size_t)bv*1024);
        CP_ASYNC16(base + SC_XV + t*16, (const void*)(Xg + t));
        const uint4* Eg = reinterpret_cast<const uint4*>(ew);
        CP_ASYNC16(base + SC_WS + t*16, (const void*)(Eg + t));
        CP_ASYNC16(base + SC_WS + (t+256)*16, (const void*)(Eg + t + 256));
        const uint4* W1g = reinterpret_cast<const uint4*>(g_W1b);
        #pragma unroll
        for (int rep = 0; rep < 8; rep++) {
            int i = t + rep*256;
            int row = i >> 5, q = i & 31;
            CP_ASYNC16(base + MO_W + row*528 + q*16, (const void*)(W1g + i));
        }
        CP_COMMIT();
    }
    CP_WAIT0();
    __syncthreads();

    // ---- fused encode ----
    {
        float* xv = (float*)(smem + SC_XV);
        float* ws = (float*)(smem + SC_WS);
        float s = 0.f, q = 0.f;
        #pragma unroll
        for (int j = 0; j < 4; j++) { float val = xv[t + 256*j]; s += val; q += val*val; }
        #pragma unroll
        for (int o = 16; o; o >>= 1) {
            s += __shfl_xor_sync(0xffffffffu, s, o);
            q += __shfl_xor_sync(0xffffffffu, q, o);
        }
        if (l == 0) { red[w] = s; red[8 + w] = q; }
        __syncthreads();
        if (t == 0) {
            float ss = 0.f, qq = 0.f;
            #pragma unroll
            for (int j = 0; j < 8; j++) { ss += red[j]; qq += red[8 + j]; }
            float mean = ss * (1.0f/LL);
            float stdv = sqrtf(qq*(1.0f/LL) - mean*mean + 1e-5f);
            g_mean[bv] = mean; g_std[bv] = stdv;
            stat[0] = mean; stat[1] = 1.0f / stdv;
        }
        __syncthreads();
        float mean = stat[0], rstd = stat[1];
        for (int i = t; i < 1024; i += 256) xv[i] = (xv[i] - mean) * rstd;
        __syncthreads();
        float* zt = (float*)(smem + MO_H1);
        for (int idx = t; idx < 8192; idx += 256) {
            int p = idx >> 7, d = idx & 127;
            float sv = __ldg(&eb[d]);
            const float* xq = &xv[p*16];
            #pragma unroll
            for (int i = 0; i < 16; i++) sv += xq[i] * ws[i*128 + d];
            zt[idx] = sv;
        }
        __syncthreads();
        __nv_bfloat16* Aimg = (__nv_bfloat16*)(smem + MO_A);
        #pragma unroll
        for (int j = 0; j < 8; j++) {
            int p = w*8 + j;
            float z[4], sv = 0.f, qv = 0.f;
            #pragma unroll
            for (int qq2 = 0; qq2 < 4; qq2++) {
                z[qq2] = zt[p*128 + l + 32*qq2];
                sv += z[qq2]; qv += z[qq2]*z[qq2];
            }
            #pragma unroll
            for (int o = 16; o; o >>= 1) {
                sv += __shfl_xor_sync(0xffffffffu, sv, o);
                qv += __shfl_xor_sync(0xffffffffu, qv, o);
            }
            float mu = sv * (1.0f/128.0f);
            float rs = rsqrtf(qv*(1.0f/128.0f) - mu*mu + 1e-5f);
            #pragma unroll
            for (int qq2 = 0; qq2 < 4; qq2++) {
                int d = l + 32*qq2;
                Aimg[d*72 + p] = __float2bfloat16((z[qq2]-mu)*rs*__ldg(&lnw[d]) + __ldg(&lnb[d]));
            }
        }
    }
    __syncthreads();

    {
        const uint4* W3g = reinterpret_cast<const uint4*>(g_W3b);
        #pragma unroll
        for (int rep = 0; rep < 8; rep++) {
            int i = t + rep*256;
            int row = i >> 2, q = i & 3;
            CP_ASYNC16(base + MO_W3 + row*80 + q*16, (const void*)(W3g + i));
        }
        issue_w2_sub(base, 0, 1, t);
    }

    // stage 1
    {
        int m0s1 = w*16;
        for (int j = 0; j < 4; j++) {
            float acc[8][4];
            #pragma unroll
            for (int i = 0; i < 8; i++)
                #pragma unroll
                for (int jj = 0; jj < 4; jj++) acc[i][jj] = 0.f;
            gemm_tile64(base + MO_A, 72, m0s1, base + MO_W, 264, j*64, 4, l, acc);
            epi64(acc, smem + MO_H1, 264, m0s1, j*64, b1g, 0, l);
        }
    }
    __syncthreads();

    int wm = w & 3, wn = w >> 2;
    int m0 = wm*32;
    float acc2[2][8][4];
    float acc3[2][4][4];
    #pragma unroll
    for (int mt = 0; mt < 2; mt++)
        #pragma unroll
        for (int j = 0; j < 4; j++)
            #pragma unroll
            for (int c = 0; c < 4; c++) acc3[mt][j][c] = 0.f;

    for (int s = 0; s < 8; s++) {
        int nc = s >> 1, ksub = s & 1;
        if (s < 7) { issue_w2_sub(base, s+1, s&1, t); CP_WAIT1(); }
        else       { CP_WAIT0(); }
        __syncthreads();
        if (ksub == 0) {
            #pragma unroll
            for (int mt = 0; mt < 2; mt++)
                #pragma unroll
                for (int j = 0; j < 8; j++)
                    #pragma unroll
                    for (int c = 0; c < 4; c++) acc2[mt][j][c] = 0.f;
        }
        uint32_t bufb = base + MO_W + ((s+1)&1)*W_SUB;
        for (int ks = 0; ks < 8; ks++) {
            int kk = ks*16;
            uint32_t a0[4], a1[4];
            ldsm4(a0, base + MO_H1 + (uint32_t)(((m0 + (l&15))*264 + ksub*128 + kk + ((l>>4)<<3))*2));
            ldsm4(a1, base + MO_H1 + (uint32_t)(((m0 + 16 + (l&15))*264 + ksub*128 + kk + ((l>>4)<<3))*2));
            #pragma unroll
            for (int tt = 0; tt < 4; tt++) {
                uint32_t bvv[4];
                ldsm4t(bvv, bufb + (uint32_t)(((kk + (l&15))*136 + wn*64 + tt*16 + ((l>>4)<<3))*2));
                mma_bf16(acc2[0][2*tt],   a0, bvv[0], bvv[1]);
                mma_bf16(acc2[0][2*tt+1], a0, bvv[2], bvv[3]);
                mma_bf16(acc2[1][2*tt],   a1, bvv[0], bvv[1]);
                mma_bf16(acc2[1][2*tt+1], a1, bvv[2], bvv[3]);
            }
        }
        if (ksub == 1) {
            #pragma unroll
            for (int kg = 0; kg < 4; kg++) {
                int krow = nc*128 + wn*64 + kg*16 + (l & 15);
                uint32_t bA[4], bB[4];
                ldsm4t(bA, base + MO_W3 + (uint32_t)((krow*40 + 0  + ((l>>4)<<3))*2));
                ldsm4t(bB, base + MO_W3 + (uint32_t)((krow*40 + 16 + ((l>>4)<<3))*2));
                int colb = nc*128 + wn*64 + kg*16 + (l&3)*2;
                float bb0 = __ldg(&b2g[colb]),     bb1 = __ldg(&b2g[colb+1]);
                float bb8 = __ldg(&b2g[colb+8]),   bb9 = __ldg(&b2g[colb+9]);
                #pragma unroll
                for (int mt = 0; mt < 2; mt++) {
                    uint32_t af[4];
                    af[0] = packrelu(acc2[mt][kg*2][0],   acc2[mt][kg*2][1],   bb0, bb1);
                    af[1] = packrelu(acc2[mt][kg*2][2],   acc2[mt][kg*2][3],   bb0, bb1);
                    af[2] = packrelu(acc2[mt][kg*2+1][0], acc2[mt][kg*2+1][1], bb8, bb9);
                    af[3] = packrelu(acc2[mt][kg*2+1][2], acc2[mt][kg*2+1][3], bb8, bb9);
                    mma_bf16(acc3[mt][0], af, bA[0], bA[1]);
                    mma_bf16(acc3[mt][1], af, bA[2], bA[3]);
                    mma_bf16(acc3[mt][2], af, bB[0], bB[1]);
                    mma_bf16(acc3[mt][3], af, bB[2], bB[3]);
                }
            }
        }
        __syncthreads();
    }

    float* OUT = (float*)(smem + MO_A);
    {
        int r = m0 + (l >> 2);
        if (wn == 0) {
            #pragma unroll
            for (int mt = 0; mt < 2; mt++)
                #pragma unroll
                for (int j = 0; j < 4; j++) {
                    int col = j*8 + (l&3)*2;
                    float b0 = __ldg(&b3g[col]), b1 = __ldg(&b3g[col+1]);
                    int rr = r + mt*16;
                    OUT[col*132 + rr]         = acc3[mt][j][0] + b0;
                    OUT[(col+1)*132 + rr]     = acc3[mt][j][1] + b1;
                    OUT[col*132 + rr + 8]     = acc3[mt][j][2] + b0;
                    OUT[(col+1)*132 + rr + 8] = acc3[mt][j][3] + b1;
                }
        }
        __syncthreads();
        if (wn == 1) {
            #pragma unroll
            for (int mt = 0; mt < 2; mt++)
                #pragma unroll
                for (int j = 0; j < 4; j++) {
                    int col = j*8 + (l&3)*2;
                    int rr = r + mt*16;
                    OUT[col*132 + rr]         += acc3[mt][j][0];
                    OUT[(col+1)*132 + rr]     += acc3[mt][j][1];
                    OUT[col*132 + rr + 8]     += acc3[mt][j][2];
                    OUT[(col+1)*132 + rr + 8] += acc3[mt][j][3];
                }
        }
        __syncthreads();
    }
    #pragma unroll
    for (int rr = 0; rr < 4; rr++) {
        int f = w*4 + rr;
        const float* Fr = OUT + f*132;
        float s = 0.f;
        #pragma unroll
        for (int j = 0; j < 4; j++) { float vv = Fr[l + 32*j]; s += vv*vv; }
        #pragma unroll
        for (int o = 16; o; o >>= 1) s += __shfl_xor_sync(0xffffffffu, s, o);
        if (l == 0) g_z2[bv*32 + f] = s;
    }
    __nv_bfloat16* zpb = g_Zpb + (size_t)bv*4096;
    for (int i = t; i < 4096; i += 256) {
        int f = i >> 7, r = i & 127;
        zpb[i] = __float2bfloat16(OUT[f*132 + r]);
    }
}

// ===== K4: HMMA VQ (M32xN64 warp tiles, double-buffered) + fused tail =====
#define VQ_ZB   0           // z_p tile [128][136]b16           34816
#define VQ_CB0  34816       // centroid buf0                    34816
#define VQ_CB1  69632       // centroid buf1                    34816
#define VQ_Z2   104448      // 512
#define VQ_C2   104960      // 4096
#define SMEM_VQ 109056
// post-mainloop overlays:
#define PQ_CVAL (VQ_CB0)            // 128*40*4 = 20480
#define PQ_CIDX (VQ_CB0 + 20480)    // 20480 (spills into CB1 head; dead later)
#define PQ_F    (VQ_CB0)            // 16896
#define PQ_DW   (VQ_CB0 + 16896)    // 8448
#define PQ_WI   (VQ_CB0 + 25344)    // 5120

__global__ void __launch_bounds__(256, 2) k_vq_mma(
    const float* __restrict__ cent, float* __restrict__ logits,
    const float* __restrict__ fb, const float* __restrict__ flnw,
    const float* __restrict__ flnb, const float* __restrict__ dwg,
    const float* __restrict__ db, float* __restrict__ out) {
    char* sm = dynsm;
    uint32_t base = smem_u32(sm);
    int t = threadIdx.x, w = t >> 5, l = t & 31;
    int n0 = blockIdx.x * 128;
    const uint4* Cg = reinterpret_cast<const uint4*>(g_Cb);

    {   // group: Z tile
        const uint4* Zg = reinterpret_cast<const uint4*>(g_Zpb) + (size_t)n0*16;
        #pragma unroll
        for (int rep = 0; rep < 8; rep++) {
            int i = t + rep*256;
            int row = i >> 4, q = i & 15;
            CP_ASYNC16(base + VQ_ZB + row*272 + q*16, (const void*)(Zg + i));
        }
        CP_COMMIT();
    }
    {   // group: chunk 0 -> CB0
        #pragma unroll
        for (int rep = 0; rep < 8; rep++) {
            int i = t + rep*256;
            int row = i >> 4, q = i & 15;
            CP_ASYNC16(base + VQ_CB0 + row*272 + q*16, (const void*)(Cg + i));
        }
        CP_COMMIT();
    }
    {
        float* c2sw = (float*)(sm + VQ_C2);
        for (int i = t; i < 1024; i += 256) c2sw[i] = g_c2[i];
        float* z2sw = (float*)(sm + VQ_Z2);
        if (t < 128) z2sw[t] = g_z2[n0 + t];
    }

    int wm = w & 3, wn = w >> 2;
    int m0 = wm*32;
    int rq = l >> 2;                    // row quad offset
    const float* c2s = (float*)(sm + VQ_C2);
    const float* z2s = (float*)(sm + VQ_Z2);

    float tv[4][5]; int ti[4][5];       // slots: rows m0+rq + {0,8,16,24}
    #pragma unroll
    for (int sl = 0; sl < 4; sl++)
        #pragma unroll
        for (int s = 0; s < 5; s++) { tv[sl][s] = 3.0e38f; ti[sl][s] = 0; }

    for (int ch = 0; ch < 8; ch++) {
        if (ch < 7) {
            uint32_t dstb = base + ((ch+1)&1 ? VQ_CB1 : VQ_CB0);
            #pragma unroll
            for (int rep = 0; rep < 8; rep++) {
                int i = t + rep*256;
                int row = i >> 4, q = i & 15;
                CP_ASYNC16(dstb + row*272 + q*16, (const void*)(Cg + (ch+1)*2048 + i));
            }
            CP_COMMIT();
            CP_WAIT1();
        } else {
            CP_WAIT0();
        }
        __syncthreads();
        uint32_t cb = base + (ch&1 ? VQ_CB1 : VQ_CB0);
        float acc[2][8][4];
        #pragma unroll
        for (int mt = 0; mt < 2; mt++)
            #pragma unroll
            for (int j = 0; j < 8; j++)
                #pragma unroll
                for (int c = 0; c < 4; c++) acc[mt][j][c] = 0.f;
        for (int ks = 0; ks < 8; ks++) {
            int kk = ks*16;
            uint32_t a0[4], a1[4];
            ldsm4(a0, base + VQ_ZB + (uint32_t)(((m0 + (l&15))*136 + kk + ((l>>4)<<3))*2));
            ldsm4(a1, base + VQ_ZB + (uint32_t)(((m0 + 16 + (l&15))*136 + kk + ((l>>4)<<3))*2));
            #pragma unroll
            for (int tt = 0; tt < 4; tt++) {
                uint32_t bvv[4];
                ldsm4(bvv, cb + (uint32_t)(((wn*64 + tt*16 + (l&15))*136 + kk + ((l>>4)<<3))*2));
                mma_bf16(acc[0][2*tt],   a0, bvv[0], bvv[2]);
                mma_bf16(acc[0][2*tt+1], a0, bvv[1], bvv[3]);
                mma_bf16(acc[1][2*tt],   a1, bvv[0], bvv[2]);
                mma_bf16(acc[1][2*tt+1], a1, bvv[1], bvv[3]);
            }
        }
        // epilogue: dist + logits + top5 (4 row slots)
        #pragma unroll
        for (int mt = 0; mt < 2; mt++) {
            int ra = m0 + mt*16 + rq, rb = ra + 8;
            float z2a = z2s[ra], z2b = z2s[rb];
            #pragma unroll
            for (int j = 0; j < 8; j++) {
                int col = ch*128 + wn*64 + (j>>1)*16 + ((j&1)<<3) + ((l&3)<<1);
                float c20 = c2s[col], c21 = c2s[col+1];
                float d00 = z2a + c20 - 2.0f*acc[mt][j][0];
                float d01 = z2a + c21 - 2.0f*acc[mt][j][1];
                float d10 = z2b + c20 - 2.0f*acc[mt][j][2];
                float d11 = z2b + c21 - 2.0f*acc[mt][j][3];
                __stcs((float2*)(logits + (size_t)(n0+ra)*1024 + col), make_float2(-d00, -d01));
                __stcs((float2*)(logits + (size_t)(n0+rb)*1024 + col), make_float2(-d10, -d11));
                top5_ins(tv[mt*2],   ti[mt*2],   d00, col); top5_ins(tv[mt*2],   ti[mt*2],   d01, col+1);
                top5_ins(tv[mt*2+1], ti[mt*2+1], d10, col); top5_ins(tv[mt*2+1], ti[mt*2+1], d11, col+1);
            }
        }
        __syncthreads();
    }

    // candidate dump: 8 owners (wn, l&3) x 5 per row
    {
        float* cval = (float*)(sm + PQ_CVAL);
        int*   cidx = (int*)(sm + PQ_CIDX);
        int own = wn*4 + (l&3);
        #pragma unroll
        for (int sl = 0; sl < 4; sl++) {
            int r = m0 + (sl>>1)*16 + (sl&1)*8 + rq;
            #pragma unroll
            for (int s = 0; s < 5; s++) {
                cval[r*40 + own*5 + s] = tv[sl][s];
                cidx[r*40 + own*5 + s] = ti[sl][s];
            }
        }
    }
    __syncthreads();
    // merge per row (staged in regs across barrier)
    float mwv[5]; int mmi[5];
    if (t < 128) {
        float* cval = (float*)(sm + PQ_CVAL);
        int*   cidx = (int*)(sm + PQ_CIDX);
        float mv[5]; int mi[5];
        #pragma unroll
        for (int s = 0; s < 5; s++) { mv[s] = 3.0e38f; mi[s] = 0; }
        for (int c = 0; c < 40; c++) top5_ins(mv, mi, cval[t*40 + c], cidx[t*40 + c]);
        float m0v = mv[0], wsum = 0.f;
        #pragma unroll
        for (int j = 0; j < 5; j++) { mwv[j] = expf(m0v - mv[j]); wsum += mwv[j]; }
        float inv = 1.0f / wsum;
        #pragma unroll
        for (int j = 0; j < 5; j++) { mwv[j] *= inv; mmi[j] = mi[j]; }
    }
    __syncthreads();   // all candidate reads done; overlays now safe
    if (t < 128) {
        float* wsm = (float*)(sm + PQ_WI);
        int*   ism = (int*)(sm + PQ_WI + 2560);
        #pragma unroll
        for (int j = 0; j < 5; j++) { wsm[t*5 + j] = mwv[j]; ism[t*5 + j] = mmi[j]; }
    }
    {
        const uint4* Fg = reinterpret_cast<const uint4*>(g_Fwb);
        for (int i = t; i < 2048; i += 256) {
            int row = i >> 4, q = i & 15;
            *(uint4*)(sm + VQ_CB1 + row*272 + q*16) = Fg[i];
        }
        float* dwT = (float*)(sm + PQ_DW);
        for (int i = t; i < 2048; i += 256) {
            int d = i >> 4, pl = i & 15;
            dwT[pl*132 + d] = dwg[i];
        }
    }
    __syncthreads();

    // fused ResidualFusion + LN + decode + denorm per bv (4 per CTA)
    float* F = (float*)(sm + PQ_F);
    float* wsm = (float*)(sm + PQ_WI);
    int*   ism = (int*)(sm + PQ_WI + 2560);
    const float* dwT = (float*)(sm + PQ_DW);
    for (int i4 = 0; i4 < 4; i4++) {
        int bvg = blockIdx.x*4 + i4;
        for (int r = w; r < 32; r += 8) {
            int gr = i4*32 + r;
            float wg[5]; int id[5];
            #pragma unroll
            for (int j = 0; j < 5; j++) { wg[j] = wsm[gr*5 + j]; id[j] = ism[gr*5 + j]; }
            int dbase = l*4;
            float4 o = make_float4(0.f,0.f,0.f,0.f);
            #pragma unroll
            for (int j = 0; j < 5; j++) {
                float4 cv = *(const float4*)&cent[(size_t)id[j]*128 + dbase];
                o.x += wg[j]*cv.x; o.y += wg[j]*cv.y;
                o.z += wg[j]*cv.z; o.w += wg[j]*cv.w;
            }
            *(float4*)&F[r*132 + dbase] = o;
        }
        __syncthreads();
        {
            int m0f = (w & 1) * 16, nb = (w >> 1) * 32;
            float facc[4][4];
            #pragma unroll
            for (int i = 0; i < 4; i++)
                #pragma unroll
                for (int j = 0; j < 4; j++) facc[i][j] = 0.f;
            for (int ks = 0; ks < 8; ks++) {
                int kk = ks*16;
                uint32_t av[4];
                ldsm4(av, base + VQ_ZB + (uint32_t)(((i4*32 + m0f + (l&15))*136 + kk + ((l>>4)<<3))*2));
                #pragma unroll
                for (int tt = 0; tt < 2; tt++) {
                    uint32_t bvv[4];
                    ldsm4t(bvv, base + VQ_CB1 + (uint32_t)(((kk + (l&15))*136 + nb + tt*16 + ((l>>4)<<3))*2));
                    mma_bf16(facc[2*tt],   av, bvv[0], bvv[1]);
                    mma_bf16(facc[2*tt+1], av, bvv[2], bvv[3]);
                }
            }
            int fr0 = m0f + (l >> 2), fr1 = fr0 + 8;
            #pragma unroll
            for (int t8 = 0; t8 < 4; t8++) {
                int col = nb + t8*8 + (l&3)*2;
                float b0 = __ldg(&fb[col]), b1 = __ldg(&fb[col+1]);
                F[fr0*132 + col]     = fmaxf(facc[t8][0] + b0, 0.f) + F[fr0*132 + col];
                F[fr0*132 + col + 1] = fmaxf(facc[t8][1] + b1, 0.f) + F[fr0*132 + col + 1];
                F[fr1*132 + col]     = fmaxf(facc[t8][2] + b0, 0.f) + F[fr1*132 + col];
                F[fr1*132 + col + 1] = fmaxf(facc[t8][3] + b1, 0.f) + F[fr1*132 + col + 1];
            }
        }
        __syncthreads();
        #pragma unroll
        for (int rr = 0; rr < 4; rr++) {
            int r = w*4 + rr;
            float vals[4], s = 0.f, q = 0.f;
            #pragma unroll
            for (int j = 0; j < 4; j++) {
                vals[j] = F[r*132 + l + 32*j];
                s += vals[j]; q += vals[j]*vals[j];
            }
            #pragma unroll
            for (int o = 16; o; o >>= 1) {
                s += __shfl_xor_sync(0xffffffffu, s, o);
                q += __shfl_xor_sync(0xffffffffu, q, o);
            }
            float mu = s * (1.0f/128.0f);
            float rs = rsqrtf(q*(1.0f/128.0f) - mu*mu + 1e-5f);
            #pragma unroll
            for (int j = 0; j < 4; j++) {
                int d = l + 32*j;
                F[r*132 + d] = (vals[j]-mu)*rs*__ldg(&flnw[d]) + __ldg(&flnb[d]);
            }
        }
        __syncthreads();
        {
            int f = t >> 3, pl = (t & 7)*2;
            float rr0 = __ldg(&db[pl]), rr1 = __ldg(&db[pl+1]);
            const float* Fr = F + f*132;
            const float* d0 = dwT + pl*132;
            const float* d1 = dwT + (pl+1)*132;
            #pragma unroll 8
            for (int d = 0; d < 128; d++) {
                float ff = Fr[d];
                rr0 += ff * d0[d];
                rr1 += ff * d1[d];
            }
            int b = bvg >> 6, v = bvg & 63;
            float stdv = g_std[bvg], meanv = g_mean[bvg];
            out[(size_t)b*32768 + (size_t)(f*16 + pl)*64 + v]     = rr0*stdv + meanv;
            out[(size_t)b*32768 + (size_t)(f*16 + pl + 1)*64 + v] = rr1*stdv + meanv;
        }
        __syncthreads();
    }
}

// ===== launch =====
extern "C" void kernel_launch(void* const* d_in, const int* in_sizes, int n_in,
                              void* d_out, int out_size) {
    const float* x      = (const float*)d_in[0];
    const float* cent   = (const float*)d_in[1];
    const float* enc_w  = (const float*)d_in[2];
    const float* enc_b  = (const float*)d_in[3];
    const float* ln_w   = (const float*)d_in[4];
    const float* ln_b   = (const float*)d_in[5];
    const float* fc1_w  = (const float*)d_in[6];
    const float* fc1_b  = (const float*)d_in[7];
    const float* fcm_w  = (const float*)d_in[8];
    const float* fcm_b  = (const float*)d_in[9];
    const float* fc2_w  = (const float*)d_in[10];
    const float* fc2_b  = (const float*)d_in[11];
    const float* fuse_w = (const float*)d_in[12];
    const float* fuse_b = (const float*)d_in[13];
    const float* fln_w  = (const float*)d_in[14];
    const float* fln_b  = (const float*)d_in[15];
    const float* dec_w  = (const float*)d_in[16];
    const float* dec_b  = (const float*)d_in[17];

    float* out    = (float*)d_out;
    float* logits = out + (size_t)BB*512*VV;

    cudaFuncSetAttribute(k_mlp_mma, cudaFuncAttributeMaxDynamicSharedMemorySize, SMEM_MLP);
    cudaFuncSetAttribute(k_vq_mma,  cudaFuncAttributeMaxDynamicSharedMemorySize, SMEM_VQ);

    k_xT<<<dim3(16, 32), 256>>>(x);
    k_prep<<<832, 256>>>(cent, fc1_w, fcm_w, fc2_w, fuse_w);
    k_mlp_mma<<<BB*VV, 256, SMEM_MLP>>>(enc_w, enc_b, ln_w, ln_b, fc1_b, fcm_b, fc2_b);
    k_vq_mma<<<NVQ/128, 256, SMEM_VQ>>>(cent, logits, fuse_b, fln_w, fln_b, dec_w, dec_b, out);
}

// round 14
// speedup vs baseline: 1.0843x; 1.0843x over previous
#include <cuda_runtime.h>
#include <cuda_bf16.h>
#include <math.h>
#include <stdint.h>

#define BB   32
#define LL   1024
#define VV   64
#define PHn  64
#define PFn  32
#define DD   128
#define KK   1024
#define NVQ  (BB*VV*PFn)
#define NROW (BB*VV*DD)

__device__ float g_mean[BB*VV];
__device__ float g_std[BB*VV];
__device__ float g_xt[(size_t)BB*VV*LL];          // x transposed [b][v][l]
__device__ float g_z2[NVQ];                       // exact fp32 |z|^2 per row
__device__ float g_c2[KK];
__device__ __nv_bfloat16 g_Zpb[(size_t)NVQ*DD];   // bf16 z_p [n][d]
__device__ __nv_bfloat16 g_Cb[(size_t)KK*DD];     // bf16 centroids [k][d]
__device__ __nv_bfloat16 g_W1b[64*256];
__device__ __nv_bfloat16 g_W2b[256*512];
__device__ __nv_bfloat16 g_W3b[512*32];
__device__ __nv_bfloat16 g_Fwb[128*128];          // bf16 fuse_w [k][n]

extern __shared__ char dynsm[];

// ===== helpers =====
__device__ __forceinline__ uint32_t smem_u32(const void* p) {
    uint32_t a;
    asm("{ .reg .u64 t; cvta.to.shared.u64 t, %1; cvt.u32.u64 %0, t; }" : "=r"(a) : "l"(p));
    return a;
}
__device__ __forceinline__ void ldsm4(uint32_t* r, uint32_t a) {
    asm volatile("ldmatrix.sync.aligned.m8n8.x4.shared.b16 {%0,%1,%2,%3}, [%4];"
        : "=r"(r[0]), "=r"(r[1]), "=r"(r[2]), "=r"(r[3]) : "r"(a));
}
__device__ __forceinline__ void ldsm4t(uint32_t* r, uint32_t a) {
    asm volatile("ldmatrix.sync.aligned.m8n8.x4.trans.shared.b16 {%0,%1,%2,%3}, [%4];"
        : "=r"(r[0]), "=r"(r[1]), "=r"(r[2]), "=r"(r[3]) : "r"(a));
}
__device__ __forceinline__ void mma_bf16(float* c, const uint32_t* a, uint32_t b0, uint32_t b1) {
    asm volatile("mma.sync.aligned.m16n8k16.row.col.f32.bf16.bf16.f32 "
        "{%0,%1,%2,%3}, {%4,%5,%6,%7}, {%8,%9}, {%0,%1,%2,%3};"
        : "+f"(c[0]), "+f"(c[1]), "+f"(c[2]), "+f"(c[3])
        : "r"(a[0]), "r"(a[1]), "r"(a[2]), "r"(a[3]), "r"(b0), "r"(b1));
}
__device__ __forceinline__ uint32_t packrelu(float x, float y, float bx, float by) {
    __nv_bfloat162 h = __float22bfloat162_rn(make_float2(fmaxf(x+bx,0.f), fmaxf(y+by,0.f)));
    return *reinterpret_cast<uint32_t*>(&h);
}
__device__ __forceinline__ void top5_ins(float* tv, int* ti, float d, int k) {
    if (d < tv[4]) {
        tv[4] = d; ti[4] = k;
        #pragma unroll
        for (int s = 4; s > 0; s--) {
            if (tv[s] < tv[s-1]) {
                float tf = tv[s]; tv[s] = tv[s-1]; tv[s-1] = tf;
                int tk = ti[s]; ti[s] = ti[s-1]; ti[s-1] = tk;
            }
        }
    }
}
#define CP_ASYNC16(dst, src) \
    asm volatile("cp.async.cg.shared.global [%0], [%1], 16;" :: "r"(dst), "l"(src))
#define CP_COMMIT() asm volatile("cp.async.commit_group;" ::: "memory")
#define CP_WAIT1()  asm volatile("cp.async.wait_group 1;" ::: "memory")
#define CP_WAIT0()  asm volatile("cp.async.wait_group 0;" ::: "memory")

// ===== K0: transpose x -> [b][v][l] =====
__global__ void __launch_bounds__(256) k_xT(const float* __restrict__ x) {
    __shared__ float tile[64][65];
    int b = blockIdx.y, l0 = blockIdx.x*64;
    int t = threadIdx.x;
    for (int i = t; i < 4096; i += 256) {
        int li = i >> 6, v = i & 63;
        tile[li][v] = x[((size_t)b*1024 + l0 + li)*64 + v];
    }
    __syncthreads();
    for (int i = t; i < 4096; i += 256) {
        int v = i >> 6, li = i & 63;
        g_xt[((size_t)b*64 + v)*1024 + l0 + li] = tile[li][v];
    }
}

// ===== K1: prep =====
__global__ void k_prep(const float* __restrict__ cent, const float* __restrict__ w1,
                       const float* __restrict__ w2, const float* __restrict__ w3,
                       const float* __restrict__ fw) {
    int blk = blockIdx.x;
    if (blk < 704) {
        int i = blk*256 + threadIdx.x;
        if (i < 16384)        g_W1b[i] = __float2bfloat16(w1[i]);
        else if (i < 147456)  g_W2b[i - 16384] = __float2bfloat16(w2[i - 16384]);
        else if (i < 163840)  g_W3b[i - 147456] = __float2bfloat16(w3[i - 147456]);
        else if (i < 180224)  g_Fwb[i - 163840] = __float2bfloat16(fw[i - 163840]);
    } else {
        int w = threadIdx.x >> 5, l = threadIdx.x & 31;
        int k = (blk - 704) * 8 + w;
        const float* cp = cent + (size_t)k*DD;
        float s = 0.f;
        #pragma unroll
        for (int q = 0; q < 4; q++) {
            float c = cp[l + 32*q];
            s += c*c;
            g_Cb[(size_t)k*DD + l + 32*q] = __float2bfloat16(c);
        }
        #pragma unroll
        for (int o = 16; o; o >>= 1) s += __shfl_xor_sync(0xffffffffu, s, o);
        if (l == 0) g_c2[k] = s;
    }
}

// ===== K3: fused encode + 3-layer HMMA MLP =====
#define MO_A   0
#define MO_W   18432
#define MO_H1  88064
#define MO_W3  155648
#define SC_XV  155648
#define SC_WS  159744
#define SMEM_MLP 196608
#define W_SUB  34816

__device__ __forceinline__ void gemm_tile64(uint32_t Abase, int sA, int m0,
                                            uint32_t Bbase, int sB, int n0,
                                            int ksteps, int l, float acc[8][4]) {
    for (int ks = 0; ks < ksteps; ks++) {
        int kk = ks*16;
        uint32_t av[4];
        ldsm4(av, Abase + (uint32_t)(((m0 + (l&15))*sA + kk + ((l>>4)<<3))*2));
        #pragma unroll
        for (int t = 0; t < 4; t++) {
            uint32_t bvv[4];
            ldsm4t(bvv, Bbase + (uint32_t)(((kk + (l&15))*sB + n0 + t*16 + ((l>>4)<<3))*2));
            mma_bf16(acc[2*t],   av, bvv[0], bvv[1]);
            mma_bf16(acc[2*t+1], av, bvv[2], bvv[3]);
        }
    }
}

__device__ __forceinline__ void epi64(float acc[8][4], char* hdst, int sH, int m0, int n0,
                                      const float* __restrict__ bias, int boff, int l) {
    int row = l >> 2, qc = (l & 3)*2;
    #pragma unroll
    for (int t8 = 0; t8 < 8; t8++) {
        int col = n0 + t8*8 + qc;
        float b0 = __ldg(&bias[boff + col]), b1 = __ldg(&bias[boff + col + 1]);
        *(uint32_t*)(hdst + ((m0+row)*sH + col)*2)   = packrelu(acc[t8][0], acc[t8][1], b0, b1);
        *(uint32_t*)(hdst + ((m0+row+8)*sH + col)*2) = packrelu(acc[t8][2], acc[t8][3], b0, b1);
    }
}

__device__ __forceinline__ void issue_w2_sub(uint32_t base, int s, int hb, int t) {
    int nc = s >> 1, ksub = s & 1;
    const uint4* W2g = reinterpret_cast<const uint4*>(g_W2b);
    #pragma unroll
    for (int rep = 0; rep < 8; rep++) {
        int i = t + rep*256;
        int row = i >> 4, q = i & 15;
        CP_ASYNC16(base + MO_W + hb*W_SUB + row*272 + q*16,
                   (const void*)(W2g + (ksub*128 + row)*64 + nc*16 + q));
    }
    CP_COMMIT();
}

__global__ void __launch_bounds__(256, 1) k_mlp_mma(
    const float* __restrict__ ew, const float* __restrict__ eb,
    const float* __restrict__ lnw, const float* __restrict__ lnb,
    const float* __restrict__ b1g, const float* __restrict__ b2g,
    const float* __restrict__ b3g) {
    char* smem = dynsm;
    uint32_t base = smem_u32(smem);
    __shared__ float red[16], stat[2];
    int t = threadIdx.x, w = t >> 5, l = t & 31;
    int bv = blockIdx.x;

    // group 0: x tile + enc_w + W1
    {
        const uint4* Xg = reinterpret_cast<const uint4*>(g_xt + (size_t)bv*1024);
        CP_ASYNC16(base + SC_XV + t*16, (const void*)(Xg + t));
        const uint4* Eg = reinterpret_cast<const uint4*>(ew);
        CP_ASYNC16(base + SC_WS + t*16, (const void*)(Eg + t));
        CP_ASYNC16(base + SC_WS + (t+256)*16, (const void*)(Eg + t + 256));
        const uint4* W1g = reinterpret_cast<const uint4*>(g_W1b);
        #pragma unroll
        for (int rep = 0; rep < 8; rep++) {
            int i = t + rep*256;
            int row = i >> 5, q = i & 31;
            CP_ASYNC16(base + MO_W + row*528 + q*16, (const void*)(W1g + i));
        }
        CP_COMMIT();
    }
    CP_WAIT0();
    __syncthreads();

    // ---- fused encode ----
    {
        float* xv = (float*)(smem + SC_XV);
        float* ws = (float*)(smem + SC_WS);
        float s = 0.f, q = 0.f;
        #pragma unroll
        for (int j = 0; j < 4; j++) { float val = xv[t + 256*j]; s += val; q += val*val; }
        #pragma unroll
        for (int o = 16; o; o >>= 1) {
            s += __shfl_xor_sync(0xffffffffu, s, o);
            q += __shfl_xor_sync(0xffffffffu, q, o);
        }
        if (l == 0) { red[w] = s; red[8 + w] = q; }
        __syncthreads();
        if (t == 0) {
            float ss = 0.f, qq = 0.f;
            #pragma unroll
            for (int j = 0; j < 8; j++) { ss += red[j]; qq += red[8 + j]; }
            float mean = ss * (1.0f/LL);
            float stdv = sqrtf(qq*(1.0f/LL) - mean*mean + 1e-5f);
            g_mean[bv] = mean; g_std[bv] = stdv;
            stat[0] = mean; stat[1] = 1.0f / stdv;
        }
        __syncthreads();
        float mean = stat[0], rstd = stat[1];
        for (int i = t; i < 1024; i += 256) xv[i] = (xv[i] - mean) * rstd;
        __syncthreads();
        float* zt = (float*)(smem + MO_H1);
        for (int idx = t; idx < 8192; idx += 256) {
            int p = idx >> 7, d = idx & 127;
            float sv = __ldg(&eb[d]);
            const float* xq = &xv[p*16];
            #pragma unroll
            for (int i = 0; i < 16; i++) sv += xq[i] * ws[i*128 + d];
            zt[idx] = sv;
        }
        __syncthreads();
        __nv_bfloat16* Aimg = (__nv_bfloat16*)(smem + MO_A);
        #pragma unroll
        for (int j = 0; j < 8; j++) {
            int p = w*8 + j;
            float z[4], sv = 0.f, qv = 0.f;
            #pragma unroll
            for (int qq2 = 0; qq2 < 4; qq2++) {
                z[qq2] = zt[p*128 + l + 32*qq2];
                sv += z[qq2]; qv += z[qq2]*z[qq2];
            }
            #pragma unroll
            for (int o = 16; o; o >>= 1) {
                sv += __shfl_xor_sync(0xffffffffu, sv, o);
                qv += __shfl_xor_sync(0xffffffffu, qv, o);
            }
            float mu = sv * (1.0f/128.0f);
            float rs = rsqrtf(qv*(1.0f/128.0f) - mu*mu + 1e-5f);
            #pragma unroll
            for (int qq2 = 0; qq2 < 4; qq2++) {
                int d = l + 32*qq2;
                Aimg[d*72 + p] = __float2bfloat16((z[qq2]-mu)*rs*__ldg(&lnw[d]) + __ldg(&lnb[d]));
            }
        }
    }
    __syncthreads();

    {
        const uint4* W3g = reinterpret_cast<const uint4*>(g_W3b);
        #pragma unroll
        for (int rep = 0; rep < 8; rep++) {
            int i = t + rep*256;
            int row = i >> 2, q = i & 3;
            CP_ASYNC16(base + MO_W3 + row*80 + q*16, (const void*)(W3g + i));
        }
        issue_w2_sub(base, 0, 1, t);
    }

    // stage 1
    {
        int m0s1 = w*16;
        for (int j = 0; j < 4; j++) {
            float acc[8][4];
            #pragma unroll
            for (int i = 0; i < 8; i++)
                #pragma unroll
                for (int jj = 0; jj < 4; jj++) acc[i][jj] = 0.f;
            gemm_tile64(base + MO_A, 72, m0s1, base + MO_W, 264, j*64, 4, l, acc);
            epi64(acc, smem + MO_H1, 264, m0s1, j*64, b1g, 0, l);
        }
    }
    __syncthreads();

    int wm = w & 3, wn = w >> 2;
    int m0 = wm*32;
    float acc2[2][8][4];
    float acc3[2][4][4];
    #pragma unroll
    for (int mt = 0; mt < 2; mt++)
        #pragma unroll
        for (int j = 0; j < 4; j++)
            #pragma unroll
            for (int c = 0; c < 4; c++) acc3[mt][j][c] = 0.f;

    for (int s = 0; s < 8; s++) {
        int nc = s >> 1, ksub = s & 1;
        if (s < 7) { issue_w2_sub(base, s+1, s&1, t); CP_WAIT1(); }
        else       { CP_WAIT0(); }
        __syncthreads();
        if (ksub == 0) {
            #pragma unroll
            for (int mt = 0; mt < 2; mt++)
                #pragma unroll
                for (int j = 0; j < 8; j++)
                    #pragma unroll
                    for (int c = 0; c < 4; c++) acc2[mt][j][c] = 0.f;
        }
        uint32_t bufb = base + MO_W + ((s+1)&1)*W_SUB;
        for (int ks = 0; ks < 8; ks++) {
            int kk = ks*16;
            uint32_t a0[4], a1[4];
            ldsm4(a0, base + MO_H1 + (uint32_t)(((m0 + (l&15))*264 + ksub*128 + kk + ((l>>4)<<3))*2));
            ldsm4(a1, base + MO_H1 + (uint32_t)(((m0 + 16 + (l&15))*264 + ksub*128 + kk + ((l>>4)<<3))*2));
            #pragma unroll
            for (int tt = 0; tt < 4; tt++) {
                uint32_t bvv[4];
                ldsm4t(bvv, bufb + (uint32_t)(((kk + (l&15))*136 + wn*64 + tt*16 + ((l>>4)<<3))*2));
                mma_bf16(acc2[0][2*tt],   a0, bvv[0], bvv[1]);
                mma_bf16(acc2[0][2*tt+1], a0, bvv[2], bvv[3]);
                mma_bf16(acc2[1][2*tt],   a1, bvv[0], bvv[1]);
                mma_bf16(acc2[1][2*tt+1], a1, bvv[2], bvv[3]);
            }
        }
        if (ksub == 1) {
            #pragma unroll
            for (int kg = 0; kg < 4; kg++) {
                int krow = nc*128 + wn*64 + kg*16 + (l & 15);
                uint32_t bA[4], bB[4];
                ldsm4t(bA, base + MO_W3 + (uint32_t)((krow*40 + 0  + ((l>>4)<<3))*2));
                ldsm4t(bB, base + MO_W3 + (uint32_t)((krow*40 + 16 + ((l>>4)<<3))*2));
                int colb = nc*128 + wn*64 + kg*16 + (l&3)*2;
                float bb0 = __ldg(&b2g[colb]),     bb1 = __ldg(&b2g[colb+1]);
                float bb8 = __ldg(&b2g[colb+8]),   bb9 = __ldg(&b2g[colb+9]);
                #pragma unroll
                for (int mt = 0; mt < 2; mt++) {
                    uint32_t af[4];
                    af[0] = packrelu(acc2[mt][kg*2][0],   acc2[mt][kg*2][1],   bb0, bb1);
                    af[1] = packrelu(acc2[mt][kg*2][2],   acc2[mt][kg*2][3],   bb0, bb1);
                    af[2] = packrelu(acc2[mt][kg*2+1][0], acc2[mt][kg*2+1][1], bb8, bb9);
                    af[3] = packrelu(acc2[mt][kg*2+1][2], acc2[mt][kg*2+1][3], bb8, bb9);
                    mma_bf16(acc3[mt][0], af, bA[0], bA[1]);
                    mma_bf16(acc3[mt][1], af, bA[2], bA[3]);
                    mma_bf16(acc3[mt][2], af, bB[0], bB[1]);
                    mma_bf16(acc3[mt][3], af, bB[2], bB[3]);
                }
            }
        }
        __syncthreads();
    }

    float* OUT = (float*)(smem + MO_A);
    {
        int r = m0 + (l >> 2);
        if (wn == 0) {
            #pragma unroll
            for (int mt = 0; mt < 2; mt++)
                #pragma unroll
                for (int j = 0; j < 4; j++) {
                    int col = j*8 + (l&3)*2;
                    float b0 = __ldg(&b3g[col]), b1 = __ldg(&b3g[col+1]);
                    int rr = r + mt*16;
                    OUT[col*132 + rr]         = acc3[mt][j][0] + b0;
                    OUT[(col+1)*132 + rr]     = acc3[mt][j][1] + b1;
                    OUT[col*132 + rr + 8]     = acc3[mt][j][2] + b0;
                    OUT[(col+1)*132 + rr + 8] = acc3[mt][j][3] + b1;
                }
        }
        __syncthreads();
        if (wn == 1) {
            #pragma unroll
            for (int mt = 0; mt < 2; mt++)
                #pragma unroll
                for (int j = 0; j < 4; j++) {
                    int col = j*8 + (l&3)*2;
                    int rr = r + mt*16;
                    OUT[col*132 + rr]         += acc3[mt][j][0];
                    OUT[(col+1)*132 + rr]     += acc3[mt][j][1];
                    OUT[col*132 + rr + 8]     += acc3[mt][j][2];
                    OUT[(col+1)*132 + rr + 8] += acc3[mt][j][3];
                }
        }
        __syncthreads();
    }
    #pragma unroll
    for (int rr = 0; rr < 4; rr++) {
        int f = w*4 + rr;
        const float* Fr = OUT + f*132;
        float s = 0.f;
        #pragma unroll
        for (int j = 0; j < 4; j++) { float vv = Fr[l + 32*j]; s += vv*vv; }
        #pragma unroll
        for (int o = 16; o; o >>= 1) s += __shfl_xor_sync(0xffffffffu, s, o);
        if (l == 0) g_z2[bv*32 + f] = s;
    }
    __nv_bfloat16* zpb = g_Zpb + (size_t)bv*4096;
    for (int i = t; i < 4096; i += 256) {
        int f = i >> 7, r = i & 127;
        zpb[i] = __float2bfloat16(OUT[f*132 + r]);
    }
}

// ===== K4: HMMA VQ (R12 tiling + A-fragments hoisted) + fused tail =====
#define VQ_ZB   0           // z_p tile [128][136]b16
#define VQ_CB0  34816
#define VQ_CB1  69632
#define VQ_Z2   104448
#define VQ_C2   104960
#define SMEM_VQ 109056
#define PQ_CVAL (VQ_CB0)            // 10240
#define PQ_CIDX (VQ_CB0 + 10240)    // 10240
#define PQ_WI   (VQ_CB0 + 20480)    // 5120
#define PQ_F    (VQ_CB0)            // 16896 (overlays dead candidates)
#define PQ_DW   (VQ_CB0 + 25600)    // 8448

__global__ void __launch_bounds__(256, 2) k_vq_mma(
    const float* __restrict__ cent, float* __restrict__ logits,
    const float* __restrict__ fb, const float* __restrict__ flnw,
    const float* __restrict__ flnb, const float* __restrict__ dwg,
    const float* __restrict__ db, float* __restrict__ out) {
    char* sm = dynsm;
    uint32_t base = smem_u32(sm);
    int t = threadIdx.x, w = t >> 5, l = t & 31;
    int n0 = blockIdx.x * 128;
    const uint4* Cg = reinterpret_cast<const uint4*>(g_Cb);

    {   // group: Z tile
        const uint4* Zg = reinterpret_cast<const uint4*>(g_Zpb) + (size_t)n0*16;
        #pragma unroll
        for (int rep = 0; rep < 8; rep++) {
            int i = t + rep*256;
            int row = i >> 4, q = i & 15;
            CP_ASYNC16(base + VQ_ZB + row*272 + q*16, (const void*)(Zg + i));
        }
        CP_COMMIT();
    }
    {   // group: chunk 0 -> CB0
        #pragma unroll
        for (int rep = 0; rep < 8; rep++) {
            int i = t + rep*256;
            int row = i >> 4, q = i & 15;
            CP_ASYNC16(base + VQ_CB0 + row*272 + q*16, (const void*)(Cg + i));
        }
        CP_COMMIT();
    }
    {
        float* c2sw = (float*)(sm + VQ_C2);
        for (int i = t; i < 1024; i += 256) c2sw[i] = g_c2[i];
        float* z2sw = (float*)(sm + VQ_Z2);
        if (t < 128) z2sw[t] = g_z2[n0 + t];
    }

    int m0 = w*16;
    int r0 = m0 + (l >> 2), r1 = r0 + 8;
    const float* c2s = (float*)(sm + VQ_C2);
    const float* z2s = (float*)(sm + VQ_Z2);

    float tv0[5], tv1[5]; int ti0[5], ti1[5];
    #pragma unroll
    for (int s = 0; s < 5; s++) { tv0[s] = 3.0e38f; tv1[s] = 3.0e38f; ti0[s] = 0; ti1[s] = 0; }

    uint32_t afr[8][4];     // A fragments, invariant across chunks/halves

    for (int ch = 0; ch < 8; ch++) {
        if (ch < 7) {
            uint32_t dstb = base + ((ch+1)&1 ? VQ_CB1 : VQ_CB0);
            #pragma unroll
            for (int rep = 0; rep < 8; rep++) {
                int i = t + rep*256;
                int row = i >> 4, q = i & 15;
                CP_ASYNC16(dstb + row*272 + q*16, (const void*)(Cg + (ch+1)*2048 + i));
            }
            CP_COMMIT();
            CP_WAIT1();      // Z + chunk ch complete; ch+1 in flight
        } else {
            CP_WAIT0();
        }
        __syncthreads();
        if (ch == 0) {       // Z tile is resident: hoist A fragments once
            #pragma unroll
            for (int ks = 0; ks < 8; ks++)
                ldsm4(afr[ks], base + VQ_ZB +
                      (uint32_t)(((m0 + (l&15))*136 + ks*16 + ((l>>4)<<3))*2));
        }
        uint32_t cb = base + (ch&1 ? VQ_CB1 : VQ_CB0);
        float z2a = z2s[r0], z2b = z2s[r1];
        for (int h = 0; h < 2; h++) {
            float acc[8][4];
            #pragma unroll
            for (int i = 0; i < 8; i++)
                #pragma unroll
                for (int j = 0; j < 4; j++) acc[i][j] = 0.f;
            #pragma unroll
            for (int ks = 0; ks < 8; ks++) {
                int kk = ks*16;
                #pragma unroll
                for (int tt = 0; tt < 4; tt++) {
                    uint32_t bvv[4];
                    ldsm4(bvv, cb + (uint32_t)(((h*64 + tt*16 + (l&15))*136 + kk + ((l>>4)<<3))*2));
                    mma_bf16(acc[2*tt],   afr[ks], bvv[0], bvv[2]);
                    mma_bf16(acc[2*tt+1], afr[ks], bvv[1], bvv[3]);
                }
            }
            int cbase = ch*128 + h*64;
            #pragma unroll
            for (int a = 0; a < 8; a++) {
                int col = cbase + (a>>1)*16 + ((a&1)<<3) + ((l&3)<<1);
                float c20 = c2s[col], c21 = c2s[col+1];
                float d00 = z2a + c20 - 2.0f*acc[a][0];
                float d01 = z2a + c21 - 2.0f*acc[a][1];
                float d10 = z2b + c20 - 2.0f*acc[a][2];
                float d11 = z2b + c21 - 2.0f*acc[a][3];
                __stcs((float2*)(logits + (size_t)(n0+r0)*1024 + col), make_float2(-d00, -d01));
                __stcs((float2*)(logits + (size_t)(n0+r1)*1024 + col), make_float2(-d10, -d11));
                top5_ins(tv0, ti0, d00, col); top5_ins(tv0, ti0, d01, col+1);
                top5_ins(tv1, ti1, d10, col); top5_ins(tv1, ti1, d11, col+1);
            }
        }
        __syncthreads();
    }

    // candidate dump into CB0 region (chunk data dead)
    {
        float* cval = (float*)(sm + PQ_CVAL);
        int*   cidx = (int*)(sm + PQ_CIDX);
        int own = l & 3;
        #pragma unroll
        for (int s = 0; s < 5; s++) {
            cval[r0*20 + own*5 + s] = tv0[s]; cidx[r0*20 + own*5 + s] = ti0[s];
            cval[r1*20 + own*5 + s] = tv1[s]; cidx[r1*20 + own*5 + s] = ti1[s];
        }
    }
    __syncthreads();
    // fuse_w -> CB1, dwT -> CB0 tail (parallel with merge below)
    {
        const uint4* Fg = reinterpret_cast<const uint4*>(g_Fwb);
        for (int i = t; i < 2048; i += 256) {
            int row = i >> 4, q = i & 15;
            *(uint4*)(sm + VQ_CB1 + row*272 + q*16) = Fg[i];
        }
        float* dwT = (float*)(sm + PQ_DW);
        for (int i = t; i < 2048; i += 256) {
            int d = i >> 4, pl = i & 15;
            dwT[pl*132 + d] = dwg[i];
        }
    }
    if (t < 128) {
        float* cval = (float*)(sm + PQ_CVAL);
        int*   cidx = (int*)(sm + PQ_CIDX);
        float mv[5]; int mi[5];
        #pragma unroll
        for (int s = 0; s < 5; s++) { mv[s] = 3.0e38f; mi[s] = 0; }
        for (int c = 0; c < 20; c++) top5_ins(mv, mi, cval[t*20 + c], cidx[t*20 + c]);
        float m0v = mv[0];
        float wv[5]; float wsum = 0.f;
        #pragma unroll
        for (int j = 0; j < 5; j++) { wv[j] = expf(m0v - mv[j]); wsum += wv[j]; }
        float inv = 1.0f / wsum;
        float* wsm = (float*)(sm + PQ_WI);
        int*   ism = (int*)(sm + PQ_WI + 2560);
        #pragma unroll
        for (int j = 0; j < 5; j++) { wsm[t*5 + j] = wv[j]*inv; ism[t*5 + j] = mi[j]; }
    }
    __syncthreads();

    // fused ResidualFusion + LN + decode + denorm per bv (4 per CTA)
    float* F = (float*)(sm + PQ_F);
    float* wsm = (float*)(sm + PQ_WI);
    int*   ism = (int*)(sm + PQ_WI + 2560);
    const float* dwT = (float*)(sm + PQ_DW);
    for (int i4 = 0; i4 < 4; i4++) {
        int bvg = blockIdx.x*4 + i4;
        for (int r = w; r < 32; r += 8) {
            int gr = i4*32 + r;
            float wg[5]; int id[5];
            #pragma unroll
            for (int j = 0; j < 5; j++) { wg[j] = wsm[gr*5 + j]; id[j] = ism[gr*5 + j]; }
            int dbase = l*4;
            float4 o = make_float4(0.f,0.f,0.f,0.f);
            #pragma unroll
            for (int j = 0; j < 5; j++) {
                float4 cv = *(const float4*)&cent[(size_t)id[j]*128 + dbase];
                o.x += wg[j]*cv.x; o.y += wg[j]*cv.y;
                o.z += wg[j]*cv.z; o.w += wg[j]*cv.w;
            }
            *(float4*)&F[r*132 + dbase] = o;
        }
        __syncthreads();
        {
            int m0f = (w & 1) * 16, nb = (w >> 1) * 32;
            float facc[4][4];
            #pragma unroll
            for (int i = 0; i < 4; i++)
                #pragma unroll
                for (int j = 0; j < 4; j++) facc[i][j] = 0.f;
            for (int ks = 0; ks < 8; ks++) {
                int kk = ks*16;
                uint32_t av[4];
                ldsm4(av, base + VQ_ZB + (uint32_t)(((i4*32 + m0f + (l&15))*136 + kk + ((l>>4)<<3))*2));
                #pragma unroll
                for (int tt = 0; tt < 2; tt++) {
                    uint32_t bvv[4];
                    ldsm4t(bvv, base + VQ_CB1 + (uint32_t)(((kk + (l&15))*136 + nb + tt*16 + ((l>>4)<<3))*2));
                    mma_bf16(facc[2*tt],   av, bvv[0], bvv[1]);
                    mma_bf16(facc[2*tt+1], av, bvv[2], bvv[3]);
                }
            }
            int fr0 = m0f + (l >> 2), fr1 = fr0 + 8;
            #pragma unroll
            for (int t8 = 0; t8 < 4; t8++) {
                int col = nb + t8*8 + (l&3)*2;
                float b0 = __ldg(&fb[col]), b1 = __ldg(&fb[col+1]);
                F[fr0*132 + col]     = fmaxf(facc[t8][0] + b0, 0.f) + F[fr0*132 + col];
                F[fr0*132 + col + 1] = fmaxf(facc[t8][1] + b1, 0.f) + F[fr0*132 + col + 1];
                F[fr1*132 + col]     = fmaxf(facc[t8][2] + b0, 0.f) + F[fr1*132 + col];
                F[fr1*132 + col + 1] = fmaxf(facc[t8][3] + b1, 0.f) + F[fr1*132 + col + 1];
            }
        }
        __syncthreads();
        #pragma unroll
        for (int rr = 0; rr < 4; rr++) {
            int r = w*4 + rr;
            float vals[4], s = 0.f, q = 0.f;
            #pragma unroll
            for (int j = 0; j < 4; j++) {
                vals[j] = F[r*132 + l + 32*j];
                s += vals[j]; q += vals[j]*vals[j];
            }
            #pragma unroll
            for (int o = 16; o; o >>= 1) {
                s += __shfl_xor_sync(0xffffffffu, s, o);
                q += __shfl_xor_sync(0xffffffffu, q, o);
            }
            float mu = s * (1.0f/128.0f);
            float rs = rsqrtf(q*(1.0f/128.0f) - mu*mu + 1e-5f);
            #pragma unroll
            for (int j = 0; j < 4; j++) {
                int d = l + 32*j;
                F[r*132 + d] = (vals[j]-mu)*rs*__ldg(&flnw[d]) + __ldg(&flnb[d]);
            }
        }
        __syncthreads();
        {
            int f = t >> 3, pl = (t & 7)*2;
            float rr0 = __ldg(&db[pl]), rr1 = __ldg(&db[pl+1]);
            const float* Fr = F + f*132;
            const float* d0 = dwT + pl*132;
            const float* d1 = dwT + (pl+1)*132;
            #pragma unroll 8
            for (int d = 0; d < 128; d++) {
                float ff = Fr[d];
                rr0 += ff * d0[d];
                rr1 += ff * d1[d];
            }
            int b = bvg >> 6, v = bvg & 63;
            float stdv = g_std[bvg], meanv = g_mean[bvg];
            out[(size_t)b*32768 + (size_t)(f*16 + pl)*64 + v]     = rr0*stdv + meanv;
            out[(size_t)b*32768 + (size_t)(f*16 + pl + 1)*64 + v] = rr1*stdv + meanv;
        }
        __syncthreads();
    }
}

// ===== launch =====
extern "C" void kernel_launch(void* const* d_in, const int* in_sizes, int n_in,
                              void* d_out, int out_size) {
    const float* x      = (const float*)d_in[0];
    const float* cent   = (const float*)d_in[1];
    const float* enc_w  = (const float*)d_in[2];
    const float* enc_b  = (const float*)d_in[3];
    const float* ln_w   = (const float*)d_in[4];
    const float* ln_b   = (const float*)d_in[5];
    const float* fc1_w  = (const float*)d_in[6];
    const float* fc1_b  = (const float*)d_in[7];
    const float* fcm_w  = (const float*)d_in[8];
    const float* fcm_b  = (const float*)d_in[9];
    const float* fc2_w  = (const float*)d_in[10];
    const float* fc2_b  = (const float*)d_in[11];
    const float* fuse_w = (const float*)d_in[12];
    const float* fuse_b = (const float*)d_in[13];
    const float* fln_w  = (const float*)d_in[14];
    const float* fln_b  = (const float*)d_in[15];
    const float* dec_w  = (const float*)d_in[16];
    const float* dec_b  = (const float*)d_in[17];

    float* out    = (float*)d_out;
    float* logits = out + (size_t)BB*512*VV;

    cudaFuncSetAttribute(k_mlp_mma, cudaFuncAttributeMaxDynamicSharedMemorySize, SMEM_MLP);
    cudaFuncSetAttribute(k_vq_mma,  cudaFuncAttributeMaxDynamicSharedMemorySize, SMEM_VQ);

    k_xT<<<dim3(16, 32), 256>>>(x);
    k_prep<<<832, 256>>>(cent, fc1_w, fcm_w, fc2_w, fuse_w);
    k_mlp_mma<<<BB*VV, 256, SMEM_MLP>>>(enc_w, enc_b, ln_w, ln_b, fc1_b, fcm_b, fc2_b);
    k_vq_mma<<<NVQ/128, 256, SMEM_VQ>>>(cent, logits, fuse_b, fln_w, fln_b, dec_w, dec_b, out);
}

// round 15
// speedup vs baseline: 1.0929x; 1.0079x over previous
#include <cuda_runtime.h>
#include <cuda_bf16.h>
#include <math.h>
#include <stdint.h>

#define BB   32
#define LL   1024
#define VV   64
#define PHn  64
#define PFn  32
#define DD   128
#define KK   1024
#define NVQ  (BB*VV*PFn)
#define NROW (BB*VV*DD)

__device__ float g_mean[BB*VV];
__device__ float g_std[BB*VV];
__device__ float g_xt[(size_t)BB*VV*LL];          // x transposed [b][v][l]
__device__ float g_z2[NVQ];                       // exact fp32 |z|^2 per row
__device__ float g_c2[KK];
__device__ __nv_bfloat16 g_Zpb[(size_t)NVQ*DD];   // bf16 z_p [n][d]
__device__ __nv_bfloat16 g_Cb[(size_t)KK*DD];     // bf16 centroids [k][d]
__device__ __nv_bfloat16 g_W1b[64*256];
__device__ __nv_bfloat16 g_W2b[256*512];
__device__ __nv_bfloat16 g_W3b[512*32];
__device__ __nv_bfloat16 g_Fwb[128*128];          // bf16 fuse_w [k][n]

extern __shared__ char dynsm[];

// ===== helpers =====
__device__ __forceinline__ uint32_t smem_u32(const void* p) {
    uint32_t a;
    asm("{ .reg .u64 t; cvta.to.shared.u64 t, %1; cvt.u32.u64 %0, t; }" : "=r"(a) : "l"(p));
    return a;
}
__device__ __forceinline__ void ldsm4(uint32_t* r, uint32_t a) {
    asm volatile("ldmatrix.sync.aligned.m8n8.x4.shared.b16 {%0,%1,%2,%3}, [%4];"
        : "=r"(r[0]), "=r"(r[1]), "=r"(r[2]), "=r"(r[3]) : "r"(a));
}
__device__ __forceinline__ void ldsm4t(uint32_t* r, uint32_t a) {
    asm volatile("ldmatrix.sync.aligned.m8n8.x4.trans.shared.b16 {%0,%1,%2,%3}, [%4];"
        : "=r"(r[0]), "=r"(r[1]), "=r"(r[2]), "=r"(r[3]) : "r"(a));
}
__device__ __forceinline__ void mma_bf16(float* c, const uint32_t* a, uint32_t b0, uint32_t b1) {
    asm volatile("mma.sync.aligned.m16n8k16.row.col.f32.bf16.bf16.f32 "
        "{%0,%1,%2,%3}, {%4,%5,%6,%7}, {%8,%9}, {%0,%1,%2,%3};"
        : "+f"(c[0]), "+f"(c[1]), "+f"(c[2]), "+f"(c[3])
        : "r"(a[0]), "r"(a[1]), "r"(a[2]), "r"(a[3]), "r"(b0), "r"(b1));
}
__device__ __forceinline__ uint32_t packrelu(float x, float y, float bx, float by) {
    __nv_bfloat162 h = __float22bfloat162_rn(make_float2(fmaxf(x+bx,0.f), fmaxf(y+by,0.f)));
    return *reinterpret_cast<uint32_t*>(&h);
}
__device__ __forceinline__ void top5_ins(float* tv, int* ti, float d, int k) {
    if (d < tv[4]) {
        tv[4] = d; ti[4] = k;
        #pragma unroll
        for (int s = 4; s > 0; s--) {
            if (tv[s] < tv[s-1]) {
                float tf = tv[s]; tv[s] = tv[s-1]; tv[s-1] = tf;
                int tk = ti[s]; ti[s] = ti[s-1]; ti[s-1] = tk;
            }
        }
    }
}
// max-top5 on e = 2*zc - c2 (larger e == smaller dist)
__device__ __forceinline__ void top5_max(float* tv, int* ti, float e, int k) {
    if (e > tv[4]) {
        tv[4] = e; ti[4] = k;
        #pragma unroll
        for (int s = 4; s > 0; s--) {
            if (tv[s] > tv[s-1]) {
                float tf = tv[s]; tv[s] = tv[s-1]; tv[s-1] = tf;
                int tk = ti[s]; ti[s] = ti[s-1]; ti[s-1] = tk;
            }
        }
    }
}
#define CP_ASYNC16(dst, src) \
    asm volatile("cp.async.cg.shared.global [%0], [%1], 16;" :: "r"(dst), "l"(src))
#define CP_COMMIT() asm volatile("cp.async.commit_group;" ::: "memory")
#define CP_WAIT1()  asm volatile("cp.async.wait_group 1;" ::: "memory")
#define CP_WAIT0()  asm volatile("cp.async.wait_group 0;" ::: "memory")

// ===== K1: prep — transpose + weight convert + centroid norms (merged) =====
__global__ void k_prep(const float* __restrict__ x, const float* __restrict__ cent,
                       const float* __restrict__ w1, const float* __restrict__ w2,
                       const float* __restrict__ w3, const float* __restrict__ fw) {
    __shared__ float tile[64][65];
    int blk = blockIdx.x;
    if (blk < 512) {                     // transpose x -> [b][v][l]
        int b = blk >> 4, l0 = (blk & 15) * 64;
        int t = threadIdx.x;
        for (int i = t; i < 4096; i += 256) {
            int li = i >> 6, v = i & 63;
            tile[li][v] = x[((size_t)b*1024 + l0 + li)*64 + v];
        }
        __syncthreads();
        for (int i = t; i < 4096; i += 256) {
            int v = i >> 6, li = i & 63;
            g_xt[((size_t)b*64 + v)*1024 + l0 + li] = tile[li][v];
        }
    } else if (blk < 1216) {             // weight bf16 convert
        int i = (blk - 512)*256 + threadIdx.x;
        if (i < 16384)        g_W1b[i] = __float2bfloat16(w1[i]);
        else if (i < 147456)  g_W2b[i - 16384] = __float2bfloat16(w2[i - 16384]);
        else if (i < 163840)  g_W3b[i - 147456] = __float2bfloat16(w3[i - 147456]);
        else if (i < 180224)  g_Fwb[i - 163840] = __float2bfloat16(fw[i - 163840]);
    } else {                             // centroid norms + bf16 copy
        int w = threadIdx.x >> 5, l = threadIdx.x & 31;
        int k = (blk - 1216) * 8 + w;
        const float* cp = cent + (size_t)k*DD;
        float s = 0.f;
        #pragma unroll
        for (int q = 0; q < 4; q++) {
            float c = cp[l + 32*q];
            s += c*c;
            g_Cb[(size_t)k*DD + l + 32*q] = __float2bfloat16(c);
        }
        #pragma unroll
        for (int o = 16; o; o >>= 1) s += __shfl_xor_sync(0xffffffffu, s, o);
        if (l == 0) g_c2[k] = s;
    }
}

// ===== K3: fused encode + 3-layer HMMA MLP =====
#define MO_A   0
#define MO_W   18432
#define MO_H1  88064
#define MO_W3  155648
#define SC_XV  155648
#define SC_WS  159744
#define SMEM_MLP 196608
#define W_SUB  34816

__device__ __forceinline__ void gemm_tile64(uint32_t Abase, int sA, int m0,
                                            uint32_t Bbase, int sB, int n0,
                                            int ksteps, int l, float acc[8][4]) {
    for (int ks = 0; ks < ksteps; ks++) {
        int kk = ks*16;
        uint32_t av[4];
        ldsm4(av, Abase + (uint32_t)(((m0 + (l&15))*sA + kk + ((l>>4)<<3))*2));
        #pragma unroll
        for (int t = 0; t < 4; t++) {
            uint32_t bvv[4];
            ldsm4t(bvv, Bbase + (uint32_t)(((kk + (l&15))*sB + n0 + t*16 + ((l>>4)<<3))*2));
            mma_bf16(acc[2*t],   av, bvv[0], bvv[1]);
            mma_bf16(acc[2*t+1], av, bvv[2], bvv[3]);
        }
    }
}

__device__ __forceinline__ void epi64(float acc[8][4], char* hdst, int sH, int m0, int n0,
                                      const float* __restrict__ bias, int boff, int l) {
    int row = l >> 2, qc = (l & 3)*2;
    #pragma unroll
    for (int t8 = 0; t8 < 8; t8++) {
        int col = n0 + t8*8 + qc;
        float b0 = __ldg(&bias[boff + col]), b1 = __ldg(&bias[boff + col + 1]);
        *(uint32_t*)(hdst + ((m0+row)*sH + col)*2)   = packrelu(acc[t8][0], acc[t8][1], b0, b1);
        *(uint32_t*)(hdst + ((m0+row+8)*sH + col)*2) = packrelu(acc[t8][2], acc[t8][3], b0, b1);
    }
}

__device__ __forceinline__ void issue_w2_sub(uint32_t base, int s, int hb, int t) {
    int nc = s >> 1, ksub = s & 1;
    const uint4* W2g = reinterpret_cast<const uint4*>(g_W2b);
    #pragma unroll
    for (int rep = 0; rep < 8; rep++) {
        int i = t + rep*256;
        int row = i >> 4, q = i & 15;
        CP_ASYNC16(base + MO_W + hb*W_SUB + row*272 + q*16,
                   (const void*)(W2g + (ksub*128 + row)*64 + nc*16 + q));
    }
    CP_COMMIT();
}

__global__ void __launch_bounds__(256, 1) k_mlp_mma(
    const float* __restrict__ ew, const float* __restrict__ eb,
    const float* __restrict__ lnw, const float* __restrict__ lnb,
    const float* __restrict__ b1g, const float* __restrict__ b2g,
    const float* __restrict__ b3g) {
    char* smem = dynsm;
    uint32_t base = smem_u32(smem);
    __shared__ float red[16], stat[2];
    int t = threadIdx.x, w = t >> 5, l = t & 31;
    int bv = blockIdx.x;

    // group 0: x tile + enc_w + W1
    {
        const uint4* Xg = reinterpret_cast<const uint4*>(g_xt + (size_t)bv*1024);
        CP_ASYNC16(base + SC_XV + t*16, (const void*)(Xg + t));
        const uint4* Eg = reinterpret_cast<const uint4*>(ew);
        CP_ASYNC16(base + SC_WS + t*16, (const void*)(Eg + t));
        CP_ASYNC16(base + SC_WS + (t+256)*16, (const void*)(Eg + t + 256));
        const uint4* W1g = reinterpret_cast<const uint4*>(g_W1b);
        #pragma unroll
        for (int rep = 0; rep < 8; rep++) {
            int i = t + rep*256;
            int row = i >> 5, q = i & 31;
            CP_ASYNC16(base + MO_W + row*528 + q*16, (const void*)(W1g + i));
        }
        CP_COMMIT();
    }
    CP_WAIT0();
    __syncthreads();

    // ---- fused encode ----
    {
        float* xv = (float*)(smem + SC_XV);
        float* ws = (float*)(smem + SC_WS);
        float s = 0.f, q = 0.f;
        #pragma unroll
        for (int j = 0; j < 4; j++) { float val = xv[t + 256*j]; s += val; q += val*val; }
        #pragma unroll
        for (int o = 16; o; o >>= 1) {
            s += __shfl_xor_sync(0xffffffffu, s, o);
            q += __shfl_xor_sync(0xffffffffu, q, o);
        }
        if (l == 0) { red[w] = s; red[8 + w] = q; }
        __syncthreads();
        if (t == 0) {
            float ss = 0.f, qq = 0.f;
            #pragma unroll
            for (int j = 0; j < 8; j++) { ss += red[j]; qq += red[8 + j]; }
            float mean = ss * (1.0f/LL);
            float stdv = sqrtf(qq*(1.0f/LL) - mean*mean + 1e-5f);
            g_mean[bv] = mean; g_std[bv] = stdv;
            stat[0] = mean; stat[1] = 1.0f / stdv;
        }
        __syncthreads();
        float mean = stat[0], rstd = stat[1];
        for (int i = t; i < 1024; i += 256) xv[i] = (xv[i] - mean) * rstd;
        __syncthreads();
        float* zt = (float*)(smem + MO_H1);
        for (int idx = t; idx < 8192; idx += 256) {
            int p = idx >> 7, d = idx & 127;
            float sv = __ldg(&eb[d]);
            const float* xq = &xv[p*16];
            #pragma unroll
            for (int i = 0; i < 16; i++) sv += xq[i] * ws[i*128 + d];
            zt[idx] = sv;
        }
        __syncthreads();
        __nv_bfloat16* Aimg = (__nv_bfloat16*)(smem + MO_A);
        #pragma unroll
        for (int j = 0; j < 8; j++) {
            int p = w*8 + j;
            float z[4], sv = 0.f, qv = 0.f;
            #pragma unroll
            for (int qq2 = 0; qq2 < 4; qq2++) {
                z[qq2] = zt[p*128 + l + 32*qq2];
                sv += z[qq2]; qv += z[qq2]*z[qq2];
            }
            #pragma unroll
            for (int o = 16; o; o >>= 1) {
                sv += __shfl_xor_sync(0xffffffffu, sv, o);
                qv += __shfl_xor_sync(0xffffffffu, qv, o);
            }
            float mu = sv * (1.0f/128.0f);
            float rs = rsqrtf(qv*(1.0f/128.0f) - mu*mu + 1e-5f);
            #pragma unroll
            for (int qq2 = 0; qq2 < 4; qq2++) {
                int d = l + 32*qq2;
                Aimg[d*72 + p] = __float2bfloat16((z[qq2]-mu)*rs*__ldg(&lnw[d]) + __ldg(&lnb[d]));
            }
        }
    }
    __syncthreads();

    {
        const uint4* W3g = reinterpret_cast<const uint4*>(g_W3b);
        #pragma unroll
        for (int rep = 0; rep < 8; rep++) {
            int i = t + rep*256;
            int row = i >> 2, q = i & 3;
            CP_ASYNC16(base + MO_W3 + row*80 + q*16, (const void*)(W3g + i));
        }
        issue_w2_sub(base, 0, 1, t);
    }

    // stage 1
    {
        int m0s1 = w*16;
        for (int j = 0; j < 4; j++) {
            float acc[8][4];
            #pragma unroll
            for (int i = 0; i < 8; i++)
                #pragma unroll
                for (int jj = 0; jj < 4; jj++) acc[i][jj] = 0.f;
            gemm_tile64(base + MO_A, 72, m0s1, base + MO_W, 264, j*64, 4, l, acc);
            epi64(acc, smem + MO_H1, 264, m0s1, j*64, b1g, 0, l);
        }
    }
    __syncthreads();

    int wm = w & 3, wn = w >> 2;
    int m0 = wm*32;
    float acc2[2][8][4];
    float acc3[2][4][4];
    #pragma unroll
    for (int mt = 0; mt < 2; mt++)
        #pragma unroll
        for (int j = 0; j < 4; j++)
            #pragma unroll
            for (int c = 0; c < 4; c++) acc3[mt][j][c] = 0.f;

    for (int s = 0; s < 8; s++) {
        int nc = s >> 1, ksub = s & 1;
        if (s < 7) { issue_w2_sub(base, s+1, s&1, t); CP_WAIT1(); }
        else       { CP_WAIT0(); }
        __syncthreads();
        if (ksub == 0) {
            #pragma unroll
            for (int mt = 0; mt < 2; mt++)
                #pragma unroll
                for (int j = 0; j < 8; j++)
                    #pragma unroll
                    for (int c = 0; c < 4; c++) acc2[mt][j][c] = 0.f;
        }
        uint32_t bufb = base + MO_W + ((s+1)&1)*W_SUB;
        for (int ks = 0; ks < 8; ks++) {
            int kk = ks*16;
            uint32_t a0[4], a1[4];
            ldsm4(a0, base + MO_H1 + (uint32_t)(((m0 + (l&15))*264 + ksub*128 + kk + ((l>>4)<<3))*2));
            ldsm4(a1, base + MO_H1 + (uint32_t)(((m0 + 16 + (l&15))*264 + ksub*128 + kk + ((l>>4)<<3))*2));
            #pragma unroll
            for (int tt = 0; tt < 4; tt++) {
                uint32_t bvv[4];
                ldsm4t(bvv, bufb + (uint32_t)(((kk + (l&15))*136 + wn*64 + tt*16 + ((l>>4)<<3))*2));
                mma_bf16(acc2[0][2*tt],   a0, bvv[0], bvv[1]);
                mma_bf16(acc2[0][2*tt+1], a0, bvv[2], bvv[3]);
                mma_bf16(acc2[1][2*tt],   a1, bvv[0], bvv[1]);
                mma_bf16(acc2[1][2*tt+1], a1, bvv[2], bvv[3]);
            }
        }
        if (ksub == 1) {
            #pragma unroll
            for (int kg = 0; kg < 4; kg++) {
                int krow = nc*128 + wn*64 + kg*16 + (l & 15);
                uint32_t bA[4], bB[4];
                ldsm4t(bA, base + MO_W3 + (uint32_t)((krow*40 + 0  + ((l>>4)<<3))*2));
                ldsm4t(bB, base + MO_W3 + (uint32_t)((krow*40 + 16 + ((l>>4)<<3))*2));
                int colb = nc*128 + wn*64 + kg*16 + (l&3)*2;
                float bb0 = __ldg(&b2g[colb]),     bb1 = __ldg(&b2g[colb+1]);
                float bb8 = __ldg(&b2g[colb+8]),   bb9 = __ldg(&b2g[colb+9]);
                #pragma unroll
                for (int mt = 0; mt < 2; mt++) {
                    uint32_t af[4];
                    af[0] = packrelu(acc2[mt][kg*2][0],   acc2[mt][kg*2][1],   bb0, bb1);
                    af[1] = packrelu(acc2[mt][kg*2][2],   acc2[mt][kg*2][3],   bb0, bb1);
                    af[2] = packrelu(acc2[mt][kg*2+1][0], acc2[mt][kg*2+1][1], bb8, bb9);
                    af[3] = packrelu(acc2[mt][kg*2+1][2], acc2[mt][kg*2+1][3], bb8, bb9);
                    mma_bf16(acc3[mt][0], af, bA[0], bA[1]);
                    mma_bf16(acc3[mt][1], af, bA[2], bA[3]);
                    mma_bf16(acc3[mt][2], af, bB[0], bB[1]);
                    mma_bf16(acc3[mt][3], af, bB[2], bB[3]);
                }
            }
        }
        __syncthreads();
    }

    float* OUT = (float*)(smem + MO_A);
    {
        int r = m0 + (l >> 2);
        if (wn == 0) {
            #pragma unroll
            for (int mt = 0; mt < 2; mt++)
                #pragma unroll
                for (int j = 0; j < 4; j++) {
                    int col = j*8 + (l&3)*2;
                    float b0 = __ldg(&b3g[col]), b1 = __ldg(&b3g[col+1]);
                    int rr = r + mt*16;
                    OUT[col*132 + rr]         = acc3[mt][j][0] + b0;
                    OUT[(col+1)*132 + rr]     = acc3[mt][j][1] + b1;
                    OUT[col*132 + rr + 8]     = acc3[mt][j][2] + b0;
                    OUT[(col+1)*132 + rr + 8] = acc3[mt][j][3] + b1;
                }
        }
        __syncthreads();
        if (wn == 1) {
            #pragma unroll
            for (int mt = 0; mt < 2; mt++)
                #pragma unroll
                for (int j = 0; j < 4; j++) {
                    int col = j*8 + (l&3)*2;
                    int rr = r + mt*16;
                    OUT[col*132 + rr]         += acc3[mt][j][0];
                    OUT[(col+1)*132 + rr]     += acc3[mt][j][1];
                    OUT[col*132 + rr + 8]     += acc3[mt][j][2];
                    OUT[(col+1)*132 + rr + 8] += acc3[mt][j][3];
                }
        }
        __syncthreads();
    }
    #pragma unroll
    for (int rr = 0; rr < 4; rr++) {
        int f = w*4 + rr;
        const float* Fr = OUT + f*132;
        float s = 0.f;
        #pragma unroll
        for (int j = 0; j < 4; j++) { float vv = Fr[l + 32*j]; s += vv*vv; }
        #pragma unroll
        for (int o = 16; o; o >>= 1) s += __shfl_xor_sync(0xffffffffu, s, o);
        if (l == 0) g_z2[bv*32 + f] = s;
    }
    __nv_bfloat16* zpb = g_Zpb + (size_t)bv*4096;
    for (int i = t; i < 4096; i += 256) {
        int f = i >> 7, r = i & 127;
        zpb[i] = __float2bfloat16(OUT[f*132 + r]);
    }
}

// ===== K4: HMMA VQ (e-trick epilogue) + fused tail =====
#define VQ_ZB   0
#define VQ_CB0  34816
#define VQ_CB1  69632
#define VQ_Z2   104448
#define VQ_C2   104960
#define SMEM_VQ 109056
#define PQ_CVAL (VQ_CB0)            // 10240
#define PQ_CIDX (VQ_CB0 + 10240)    // 10240
#define PQ_WI   (VQ_CB0 + 20480)    // 5120
#define PQ_F    (VQ_CB0)            // 16896 (overlays dead candidates)
#define PQ_DW   (VQ_CB0 + 25600)    // 8448

__global__ void __launch_bounds__(256, 2) k_vq_mma(
    const float* __restrict__ cent, float* __restrict__ logits,
    const float* __restrict__ fb, const float* __restrict__ flnw,
    const float* __restrict__ flnb, const float* __restrict__ dwg,
    const float* __restrict__ db, float* __restrict__ out) {
    char* sm = dynsm;
    uint32_t base = smem_u32(sm);
    int t = threadIdx.x, w = t >> 5, l = t & 31;
    int n0 = blockIdx.x * 128;
    const uint4* Cg = reinterpret_cast<const uint4*>(g_Cb);

    {   // group: Z tile
        const uint4* Zg = reinterpret_cast<const uint4*>(g_Zpb) + (size_t)n0*16;
        #pragma unroll
        for (int rep = 0; rep < 8; rep++) {
            int i = t + rep*256;
            int row = i >> 4, q = i & 15;
            CP_ASYNC16(base + VQ_ZB + row*272 + q*16, (const void*)(Zg + i));
        }
        CP_COMMIT();
    }
    {   // group: chunk 0 -> CB0
        #pragma unroll
        for (int rep = 0; rep < 8; rep++) {
            int i = t + rep*256;
            int row = i >> 4, q = i & 15;
            CP_ASYNC16(base + VQ_CB0 + row*272 + q*16, (const void*)(Cg + i));
        }
        CP_COMMIT();
    }
    {
        float* c2sw = (float*)(sm + VQ_C2);
        for (int i = t; i < 1024; i += 256) c2sw[i] = g_c2[i];
        float* z2sw = (float*)(sm + VQ_Z2);
        if (t < 128) z2sw[t] = g_z2[n0 + t];
    }

    int m0 = w*16;
    int r0 = m0 + (l >> 2), r1 = r0 + 8;
    const float* c2s = (float*)(sm + VQ_C2);
    const float* z2s = (float*)(sm + VQ_Z2);

    float tv0[5], tv1[5]; int ti0[5], ti1[5];
    #pragma unroll
    for (int s = 0; s < 5; s++) { tv0[s] = -3.0e38f; tv1[s] = -3.0e38f; ti0[s] = 0; ti1[s] = 0; }

    uint32_t afr[8][4];     // A fragments, invariant across chunks/halves

    for (int ch = 0; ch < 8; ch++) {
        if (ch < 7) {
            uint32_t dstb = base + ((ch+1)&1 ? VQ_CB1 : VQ_CB0);
            #pragma unroll
            for (int rep = 0; rep < 8; rep++) {
                int i = t + rep*256;
                int row = i >> 4, q = i & 15;
                CP_ASYNC16(dstb + row*272 + q*16, (const void*)(Cg + (ch+1)*2048 + i));
            }
            CP_COMMIT();
            CP_WAIT1();
        } else {
            CP_WAIT0();
        }
        __syncthreads();
        if (ch == 0) {
            #pragma unroll
            for (int ks = 0; ks < 8; ks++)
                ldsm4(afr[ks], base + VQ_ZB +
                      (uint32_t)(((m0 + (l&15))*136 + ks*16 + ((l>>4)<<3))*2));
        }
        uint32_t cb = base + (ch&1 ? VQ_CB1 : VQ_CB0);
        float z2a = z2s[r0], z2b = z2s[r1];
        for (int h = 0; h < 2; h++) {
            float acc[8][4];
            #pragma unroll
            for (int i = 0; i < 8; i++)
                #pragma unroll
                for (int j = 0; j < 4; j++) acc[i][j] = 0.f;
            #pragma unroll
            for (int ks = 0; ks < 8; ks++) {
                int kk = ks*16;
                #pragma unroll
                for (int tt = 0; tt < 4; tt++) {
                    uint32_t bvv[4];
                    ldsm4(bvv, cb + (uint32_t)(((h*64 + tt*16 + (l&15))*136 + kk + ((l>>4)<<3))*2));
                    mma_bf16(acc[2*tt],   afr[ks], bvv[0], bvv[2]);
                    mma_bf16(acc[2*tt+1], afr[ks], bvv[1], bvv[3]);
                }
            }
            int cbase = ch*128 + h*64;
            #pragma unroll
            for (int a = 0; a < 8; a++) {
                int col = cbase + (a>>1)*16 + ((a&1)<<3) + ((l&3)<<1);
                float c20 = c2s[col], c21 = c2s[col+1];
                // e = 2*zc - c2; logits = e - z2; selection on e (max)
                float e00 = fmaf(2.0f, acc[a][0], -c20);
                float e01 = fmaf(2.0f, acc[a][1], -c21);
                float e10 = fmaf(2.0f, acc[a][2], -c20);
                float e11 = fmaf(2.0f, acc[a][3], -c21);
                __stcs((float2*)(logits + (size_t)(n0+r0)*1024 + col), make_float2(e00 - z2a, e01 - z2a));
                __stcs((float2*)(logits + (size_t)(n0+r1)*1024 + col), make_float2(e10 - z2b, e11 - z2b));
                top5_max(tv0, ti0, e00, col); top5_max(tv0, ti0, e01, col+1);
                top5_max(tv1, ti1, e10, col); top5_max(tv1, ti1, e11, col+1);
            }
        }
        __syncthreads();
    }

    // candidate dump into CB0 region (chunk data dead)
    {
        float* cval = (float*)(sm + PQ_CVAL);
        int*   cidx = (int*)(sm + PQ_CIDX);
        int own = l & 3;
        #pragma unroll
        for (int s = 0; s < 5; s++) {
            cval[r0*20 + own*5 + s] = tv0[s]; cidx[r0*20 + own*5 + s] = ti0[s];
            cval[r1*20 + own*5 + s] = tv1[s]; cidx[r1*20 + own*5 + s] = ti1[s];
        }
    }
    __syncthreads();
    {
        const uint4* Fg = reinterpret_cast<const uint4*>(g_Fwb);
        for (int i = t; i < 2048; i += 256) {
            int row = i >> 4, q = i & 15;
            *(uint4*)(sm + VQ_CB1 + row*272 + q*16) = Fg[i];
        }
        float* dwT = (float*)(sm + PQ_DW);
        for (int i = t; i < 2048; i += 256) {
            int d = i >> 4, pl = i & 15;
            dwT[pl*132 + d] = dwg[i];
        }
    }
    if (t < 128) {
        float* cval = (float*)(sm + PQ_CVAL);
        int*   cidx = (int*)(sm + PQ_CIDX);
        float mv[5]; int mi[5];
        #pragma unroll
        for (int s = 0; s < 5; s++) { mv[s] = -3.0e38f; mi[s] = 0; }
        for (int c = 0; c < 20; c++) top5_max(mv, mi, cval[t*20 + c], cidx[t*20 + c]);
        float m0v = mv[0];
        float wv[5]; float wsum = 0.f;
        #pragma unroll
        for (int j = 0; j < 5; j++) { wv[j] = expf(mv[j] - m0v); wsum += wv[j]; }
        float inv = 1.0f / wsum;
        float* wsm = (float*)(sm + PQ_WI);
        int*   ism = (int*)(sm + PQ_WI + 2560);
        #pragma unroll
        for (int j = 0; j < 5; j++) { wsm[t*5 + j] = wv[j]*inv; ism[t*5 + j] = mi[j]; }
    }
    __syncthreads();

    // fused ResidualFusion + LN + decode + denorm per bv (4 per CTA)
    float* F = (float*)(sm + PQ_F);
    float* wsm = (float*)(sm + PQ_WI);
    int*   ism = (int*)(sm + PQ_WI + 2560);
    const float* dwT = (float*)(sm + PQ_DW);
    for (int i4 = 0; i4 < 4; i4++) {
        int bvg = blockIdx.x*4 + i4;
        for (int r = w; r < 32; r += 8) {
            int gr = i4*32 + r;
            float wg[5]; int id[5];
            #pragma unroll
            for (int j = 0; j < 5; j++) { wg[j] = wsm[gr*5 + j]; id[j] = ism[gr*5 + j]; }
            int dbase = l*4;
            float4 o = make_float4(0.f,0.f,0.f,0.f);
            #pragma unroll
            for (int j = 0; j < 5; j++) {
                float4 cv = *(const float4*)&cent[(size_t)id[j]*128 + dbase];
                o.x += wg[j]*cv.x; o.y += wg[j]*cv.y;
                o.z += wg[j]*cv.z; o.w += wg[j]*cv.w;
            }
            *(float4*)&F[r*132 + dbase] = o;
        }
        __syncthreads();
        {
            int m0f = (w & 1) * 16, nb = (w >> 1) * 32;
            float facc[4][4];
            #pragma unroll
            for (int i = 0; i < 4; i++)
                #pragma unroll
                for (int j = 0; j < 4; j++) facc[i][j] = 0.f;
            for (int ks = 0; ks < 8; ks++) {
                int kk = ks*16;
                uint32_t av[4];
                ldsm4(av, base + VQ_ZB + (uint32_t)(((i4*32 + m0f + (l&15))*136 + kk + ((l>>4)<<3))*2));
                #pragma unroll
                for (int tt = 0; tt < 2; tt++) {
                    uint32_t bvv[4];
                    ldsm4t(bvv, base + VQ_CB1 + (uint32_t)(((kk + (l&15))*136 + nb + tt*16 + ((l>>4)<<3))*2));
                    mma_bf16(facc[2*tt],   av, bvv[0], bvv[1]);
                    mma_bf16(facc[2*tt+1], av, bvv[2], bvv[3]);
                }
            }
            int fr0 = m0f + (l >> 2), fr1 = fr0 + 8;
            #pragma unroll
            for (int t8 = 0; t8 < 4; t8++) {
                int col = nb + t8*8 + (l&3)*2;
                float b0 = __ldg(&fb[col]), b1 = __ldg(&fb[col+1]);
                F[fr0*132 + col]     = fmaxf(facc[t8][0] + b0, 0.f) + F[fr0*132 + col];
                F[fr0*132 + col + 1] = fmaxf(facc[t8][1] + b1, 0.f) + F[fr0*132 + col + 1];
                F[fr1*132 + col]     = fmaxf(facc[t8][2] + b0, 0.f) + F[fr1*132 + col];
                F[fr1*132 + col + 1] = fmaxf(facc[t8][3] + b1, 0.f) + F[fr1*132 + col + 1];
            }
        }
        __syncthreads();
        #pragma unroll
        for (int rr = 0; rr < 4; rr++) {
            int r = w*4 + rr;
            float vals[4], s = 0.f, q = 0.f;
            #pragma unroll
            for (int j = 0; j < 4; j++) {
                vals[j] = F[r*132 + l + 32*j];
                s += vals[j]; q += vals[j]*vals[j];
            }
            #pragma unroll
            for (int o = 16; o; o >>= 1) {
                s += __shfl_xor_sync(0xffffffffu, s, o);
                q += __shfl_xor_sync(0xffffffffu, q, o);
            }
            float mu = s * (1.0f/128.0f);
            float rs = rsqrtf(q*(1.0f/128.0f) - mu*mu + 1e-5f);
            #pragma unroll
            for (int j = 0; j < 4; j++) {
                int d = l + 32*j;
                F[r*132 + d] = (vals[j]-mu)*rs*__ldg(&flnw[d]) + __ldg(&flnb[d]);
            }
        }
        __syncthreads();
        {
            int f = t >> 3, pl = (t & 7)*2;
            float rr0 = __ldg(&db[pl]), rr1 = __ldg(&db[pl+1]);
            const float* Fr = F + f*132;
            const float* d0 = dwT + pl*132;
            const float* d1 = dwT + (pl+1)*132;
            #pragma unroll 8
            for (int d = 0; d < 128; d++) {
                float ff = Fr[d];
                rr0 += ff * d0[d];
                rr1 += ff * d1[d];
            }
            int b = bvg >> 6, v = bvg & 63;
            float stdv = g_std[bvg], meanv = g_mean[bvg];
            out[(size_t)b*32768 + (size_t)(f*16 + pl)*64 + v]     = rr0*stdv + meanv;
            out[(size_t)b*32768 + (size_t)(f*16 + pl + 1)*64 + v] = rr1*stdv + meanv;
        }
        __syncthreads();
    }
}

// ===== launch =====
extern "C" void kernel_launch(void* const* d_in, const int* in_sizes, int n_in,
                              void* d_out, int out_size) {
    const float* x      = (const float*)d_in[0];
    const float* cent   = (const float*)d_in[1];
    const float* enc_w  = (const float*)d_in[2];
    const float* enc_b  = (const float*)d_in[3];
    const float* ln_w   = (const float*)d_in[4];
    const float* ln_b   = (const float*)d_in[5];
    const float* fc1_w  = (const float*)d_in[6];
    const float* fc1_b  = (const float*)d_in[7];
    const float* fcm_w  = (const float*)d_in[8];
    const float* fcm_b  = (const float*)d_in[9];
    const float* fc2_w  = (const float*)d_in[10];
    const float* fc2_b  = (const float*)d_in[11];
    const float* fuse_w = (const float*)d_in[12];
    const float* fuse_b = (const float*)d_in[13];
    const float* fln_w  = (const float*)d_in[14];
    const float* fln_b  = (const float*)d_in[15];
    const float* dec_w  = (const float*)d_in[16];
    const float* dec_b  = (const float*)d_in[17];

    float* out    = (float*)d_out;
    float* logits = out + (size_t)BB*512*VV;

    cudaFuncSetAttribute(k_mlp_mma, cudaFuncAttributeMaxDynamicSharedMemorySize, SMEM_MLP);
    cudaFuncSetAttribute(k_vq_mma,  cudaFuncAttributeMaxDynamicSharedMemorySize, SMEM_VQ);

    k_prep<<<1344, 256>>>(x, cent, fc1_w, fcm_w, fc2_w, fuse_w);
    k_mlp_mma<<<BB*VV, 256, SMEM_MLP>>>(enc_w, enc_b, ln_w, ln_b, fc1_b, fcm_b, fc2_b);
    k_vq_mma<<<NVQ/128, 256, SMEM_VQ>>>(cent, logits, fuse_b, fln_w, fln_b, dec_w, dec_b, out);
}